// round 9
// baseline (speedup 1.0000x reference)
#include <cuda_runtime.h>

#define NQ       12
#define DIM      4096
#define THREADS  256
#define NCLASSES 10
#define NFEAT    36

typedef unsigned long long u64;

struct Cx { float x, y; };
__device__ __forceinline__ Cx cmul(Cx a, Cx b) {
    return Cx{a.x * b.x - a.y * b.y, a.x * b.y + a.y * b.x};
}

// ---- f32x2 helpers ----
__device__ __forceinline__ u64 pk(float lo, float hi) {
    u64 r; asm("mov.b64 %0, {%1,%2};" : "=l"(r) : "f"(lo), "f"(hi)); return r;
}
__device__ __forceinline__ void upk(u64 v, float& lo, float& hi) {
    asm("mov.b64 {%0,%1}, %2;" : "=f"(lo), "=f"(hi) : "l"(v));
}
__device__ __forceinline__ u64 f2fma(u64 a, u64 b, u64 c) {
    u64 r; asm("fma.rn.f32x2 %0, %1, %2, %3;" : "=l"(r) : "l"(a), "l"(b), "l"(c)); return r;
}
__device__ __forceinline__ u64 f2mul(u64 a, u64 b) {
    u64 r; asm("mul.rn.f32x2 %0, %1, %2;" : "=l"(r) : "l"(a), "l"(b)); return r;
}
__device__ __forceinline__ u64 f2add(u64 a, u64 b) {
    u64 r; asm("add.rn.f32x2 %0, %1, %2;" : "=l"(r) : "l"(a), "l"(b)); return r;
}
__device__ __forceinline__ u64 splat(float x) { return pk(x, x); }
__device__ __forceinline__ u64 swap2(u64 v) { float lo, hi; upk(v, lo, hi); return pk(hi, lo); }

// ---- addressing ----
__device__ __forceinline__ int swzc(int i) { return i ^ ((i >> 5) & 31); }

template<int S1,int S2,int S3>
__device__ __forceinline__ int offm(int m) {
    return ((m & 1) << S1) | (((m >> 1) & 1) << S2) | (((m >> 2) & 1) << S3);
}
template<int L0,int L1,int L2,int L3,int L4,int W0,int W1,int W2>
__device__ __forceinline__ int mkbase(int t) {
    return ((t & 1) << L0) | (((t >> 1) & 1) << L1) | (((t >> 2) & 1) << L2) |
           (((t >> 3) & 1) << L3) | (((t >> 4) & 1) << L4) |
           (((t >> 5) & 1) << W0) | (((t >> 6) & 1) << W1) | (((t >> 7) & 1) << W2);
}

template<int S0,int S1,int S2,int S3>
__device__ __forceinline__ void vld(u64 R[8], u64 I[8], const float2* cx, int pb) {
    const int d = swzc(1 << S0);
#pragma unroll
    for (int m = 0; m < 8; m++) {
        const int ad0 = pb ^ swzc(offm<S1,S2,S3>(m));
        const float2 v0 = cx[ad0];
        const float2 v1 = cx[ad0 ^ d];
        R[m] = pk(v0.x, v1.x);
        I[m] = pk(v0.y, v1.y);
    }
}
template<int S0,int S1,int S2,int S3>
__device__ __forceinline__ void vst(const u64 R[8], const u64 I[8], float2* cx, int pb) {
    const int d = swzc(1 << S0);
#pragma unroll
    for (int m = 0; m < 8; m++) {
        const int ad0 = pb ^ swzc(offm<S1,S2,S3>(m));
        float r0, r1, i0, i1;
        upk(R[m], r0, r1); upk(I[m], i0, i1);
        cx[ad0]     = make_float2(r0, i0);
        cx[ad0 ^ d] = make_float2(r1, i1);
    }
}

// ---- gate bodies ----
// SU(2): U = [[u00,u01],[-u01*,u00*]]
// GS: [0]=u00x [1]=u01x [2]=u00y [3]=u01y [4]=-u00y [5]=-u01y [6]=-u01x
#define V1Q_BODY(mlo, mhi) do {                                                  \
    const u64 a = R[mlo], ai = I[mlo], b = R[mhi], bi = I[mhi];                  \
    R[mlo] = f2fma(g0, a, f2fma(g4, ai, f2fma(g1, b, f2mul(g5, bi))));           \
    I[mlo] = f2fma(g2, a, f2fma(g0, ai, f2fma(g3, b, f2mul(g1, bi))));           \
    R[mhi] = f2fma(g6, a, f2fma(g5, ai, f2fma(g0, b, f2mul(g2, bi))));           \
    I[mhi] = f2fma(g3, a, f2fma(g6, ai, f2fma(g4, b, f2mul(g0, bi))));           \
} while (0)

template<int K>
__device__ __forceinline__ void v1q(u64 R[8], u64 I[8], const u64* g) {
    const u64 g0 = g[0], g1 = g[1], g2 = g[2], g3 = g[3], g4 = g[4], g5 = g[5], g6 = g[6];
#pragma unroll
    for (int m = 0; m < 8; m++) {
        if (!((m >> (K-1)) & 1)) { const int m1 = m | (1 << (K-1)); V1Q_BODY(m, m1); }
    }
}
template<int K>  // first gate, state purely real
__device__ __forceinline__ void v1q_real(u64 R[8], u64 I[8], const u64* g) {
    const u64 g0 = g[0], g1 = g[1], g2 = g[2], g3 = g[3], g4 = g[4], g6 = g[6];
#pragma unroll
    for (int m = 0; m < 8; m++) {
        if (!((m >> (K-1)) & 1)) {
            const int m1 = m | (1 << (K-1));
            const u64 a = R[m], b = R[m1];
            R[m]  = f2fma(g0, a, f2mul(g1, b));
            I[m]  = f2fma(g2, a, f2mul(g3, b));
            R[m1] = f2fma(g6, a, f2mul(g0, b));
            I[m1] = f2fma(g3, a, f2mul(g4, b));
        }
    }
}
// Controlled 1q: ctrl tile bit KC, tgt tile bit KT. ctrl=0 -> gu, ctrl=1 -> gv.
template<int KC,int KT>
__device__ __forceinline__ void c1q(u64 R[8], u64 I[8], const u64* gu, const u64* gv) {
    {
        const u64 g0 = gu[0], g1 = gu[1], g2 = gu[2], g3 = gu[3], g4 = gu[4], g5 = gu[5], g6 = gu[6];
#pragma unroll
        for (int m = 0; m < 8; m++)
            if (!((m >> (KT-1)) & 1) && !((m >> (KC-1)) & 1)) { const int m1 = m | (1 << (KT-1)); V1Q_BODY(m, m1); }
    }
    {
        const u64 g0 = gv[0], g1 = gv[1], g2 = gv[2], g3 = gv[3], g4 = gv[4], g5 = gv[5], g6 = gv[6];
#pragma unroll
        for (int m = 0; m < 8; m++)
            if (!((m >> (KT-1)) & 1) && ((m >> (KC-1)) & 1)) { const int m1 = m | (1 << (KT-1)); V1Q_BODY(m, m1); }
    }
}

// 1q on packed lane bit: GP: [0]A={u00x,-u01x} [1]B={u01x,u00x} [2]C={u00y,u01y} [3]D={u01y,-u00y} [4]-C [5]-D
#define V2Q_BODY(m) do {                                                          \
    float ar0, ar1, ai0, ai1;                                                     \
    upk(R[m], ar0, ar1); upk(I[m], ai0, ai1);                                     \
    const u64 sr0 = splat(ar0), sr1 = splat(ar1), si0 = splat(ai0), si1 = splat(ai1); \
    R[m] = f2fma(A, sr0, f2fma(Cn, si0, f2fma(B, sr1, f2mul(Dn, si1))));          \
    I[m] = f2fma(C, sr0, f2fma(A,  si0, f2fma(D, sr1, f2mul(B,  si1))));          \
} while (0)

__device__ __forceinline__ void v2q(u64 R[8], u64 I[8], const u64* p) {
    const u64 A = p[0], B = p[1], C = p[2], D = p[3], Cn = p[4], Dn = p[5];
#pragma unroll
    for (int m = 0; m < 8; m++) { V2Q_BODY(m); }
}
// Controlled packed-bit 1q: ctrl tile bit KC. ctrl=0 -> pu, ctrl=1 -> pv.
template<int KC>
__device__ __forceinline__ void cv2q(u64 R[8], u64 I[8], const u64* pu, const u64* pv) {
    {
        const u64 A = pu[0], B = pu[1], C = pu[2], D = pu[3], Cn = pu[4], Dn = pu[5];
#pragma unroll
        for (int m = 0; m < 8; m++) if (!((m >> (KC-1)) & 1)) { V2Q_BODY(m); }
    }
    {
        const u64 A = pv[0], B = pv[1], C = pv[2], D = pv[3], Cn = pv[4], Dn = pv[5];
#pragma unroll
        for (int m = 0; m < 8; m++) if (((m >> (KC-1)) & 1)) { V2Q_BODY(m); }
    }
}

// CRX variants (unfused remainder)
template<int KC,int KT>
__device__ __forceinline__ void vcrx(u64 R[8], u64 I[8], const u64* q) {
    const u64 q0 = q[0], q1 = q[1], q2 = q[2];
#pragma unroll
    for (int m = 0; m < 8; m++) {
        if (((m >> (KC-1)) & 1) && !((m >> (KT-1)) & 1)) {
            const int m1 = m | (1 << (KT-1));
            const u64 a = R[m], ai = I[m], b = R[m1], bi = I[m1];
            R[m]  = f2fma(q0, a,  f2mul(q1, bi));
            I[m]  = f2fma(q0, ai, f2mul(q2, b));
            R[m1] = f2fma(q0, b,  f2mul(q1, ai));
            I[m1] = f2fma(q0, bi, f2mul(q2, a));
        }
    }
}
template<int KC>
__device__ __forceinline__ void vcrx0t(u64 R[8], u64 I[8], const u64* q) {
    const u64 q0 = q[0], q1 = q[1], q2 = q[2];
#pragma unroll
    for (int m = 0; m < 8; m++) {
        if ((m >> (KC-1)) & 1) {
            const u64 swI = swap2(I[m]), swR = swap2(R[m]);
            R[m] = f2fma(q0, R[m], f2mul(q1, swI));
            I[m] = f2fma(q0, I[m], f2mul(q2, swR));
        }
    }
}
template<int KT>
__device__ __forceinline__ void vcrx0c(u64 R[8], u64 I[8], const u64* q) {
    const u64 q0 = q[0], q1 = q[1], q2 = q[2];
#pragma unroll
    for (int m = 0; m < 8; m++) {
        if (!((m >> (KT-1)) & 1)) {
            const int m1 = m | (1 << (KT-1));
            const u64 Ra = R[m], Ia = I[m], Rb = R[m1], Ib = I[m1];
            R[m]  = f2fma(q0, Ra, f2mul(q1, Ib));
            I[m]  = f2fma(q0, Ia, f2mul(q2, Rb));
            R[m1] = f2fma(q0, Rb, f2mul(q1, Ia));
            I[m1] = f2fma(q0, Ib, f2mul(q2, Ra));
        }
    }
}

__device__ __forceinline__ void red_add(float v, float* dst) {
#pragma unroll
    for (int o = 16; o > 0; o >>= 1) v += __shfl_xor_sync(0xffffffffu, v, o);
    if ((threadIdx.x & 31) == 0) atomicAdd(dst, v);
}

template<int K>
__device__ __forceinline__ void vcross(const u64 R[8], const u64 I[8], float* feats, int q) {
    u64 cr2 = 0ull, cip = 0ull, cin = 0ull;
#pragma unroll
    for (int m = 0; m < 8; m++) {
        if (!((m >> (K-1)) & 1)) {
            const int m1 = m | (1 << (K-1));
            cr2 = f2fma(R[m], R[m1], f2fma(I[m], I[m1], cr2));
            cip = f2fma(R[m], I[m1], cip);
            cin = f2fma(I[m], R[m1], cin);
        }
    }
    float a, b;  upk(cr2, a, b); const float cr = a + b;
    float p0, p1, n0, n1; upk(cip, p0, p1); upk(cin, n0, n1);
    red_add(2.f * cr, &feats[q]);
    red_add(2.f * ((p0 - n0) + (p1 - n1)), &feats[NQ + q]);
}
__device__ __forceinline__ void vcross0(const u64 R[8], const u64 I[8], float* feats, int q) {
    float cr = 0.f, ci = 0.f;
#pragma unroll
    for (int m = 0; m < 8; m++) {
        float r0, r1, i0, i1;
        upk(R[m], r0, r1); upk(I[m], i0, i1);
        cr = fmaf(r0, r1, fmaf(i0, i1, cr));
        ci = fmaf(r0, i1, ci) - i0 * r1;
    }
    red_add(2.f * cr, &feats[q]);
    red_add(2.f * ci, &feats[NQ + q]);
}

// Compute fused-1q matrix U for (layer, wire) from angles.
__device__ __forceinline__ void fused_u(const float* angles, int layer, int wire, Cx& u00, Cx& u01) {
    const int base = layer * 48;
    const float tx = angles[base + wire];
    const float ty = angles[base + 12 + wire];
    const float tz = angles[base + 24 + wire];
    const float cxv = cosf(0.5f*tx), sxv = sinf(0.5f*tx);
    const float cyv = cosf(0.5f*ty), syv = sinf(0.5f*ty);
    const float czv = cosf(0.5f*tz), szv = sinf(0.5f*tz);
    Cx m00{cyv*cxv,  syv*sxv};
    Cx m01{-syv*cxv, -cyv*sxv};
    Cx ezm{czv, -szv};
    u00 = cmul(ezm, m00);
    u01 = cmul(ezm, m01);
}
// V = RX(theta) * U
__device__ __forceinline__ void rx_compose(Cx u00, Cx u01, float c, float s, Cx& v00, Cx& v01) {
    v00 = Cx{c*u00.x + s*u01.y, c*u00.y + s*u01.x};
    v01 = Cx{c*u01.x - s*u00.y, c*u01.y - s*u00.x};
}

__global__ __launch_bounds__(THREADS, 3)
void qsim_kernel(const float* __restrict__ sv,
                 const float* __restrict__ angles,
                 const float* __restrict__ Wm,
                 const float* __restrict__ bv,
                 float* __restrict__ out)
{
    __shared__ float2 cx[DIM];        // interleaved (re, im), 32 KB
    __shared__ u64 GS[24][8];         // SU(2) 7-coef splatted
    __shared__ u64 GP[24][6];         // lane-packed (packed-bit 1q)
    __shared__ u64 CC[24][3];
    __shared__ u64 CL[24][3];
    __shared__ u64 FGS[7][8];         // fused V = RX*U, GS layout (tile-ctrl c1q)
    __shared__ u64 FGP[4][6];         // fused V, GP layout (cv2q)
    __shared__ u64 LPQ[8];            // lane-packed {U, RX*U} (P4 L1 w0 + CRX(11,0))
    __shared__ float feats[NFEAT];

    const int tid  = threadIdx.x;
    const int bidx = blockIdx.x;

    if (tid < 24) {
        const int layer = tid / NQ;
        const int wire  = tid % NQ;
        Cx u00, u01;
        fused_u(angles, layer, wire, u00, u01);
        GS[tid][0] = splat(u00.x);  GS[tid][1] = splat(u01.x);
        GS[tid][2] = splat(u00.y);  GS[tid][3] = splat(u01.y);
        GS[tid][4] = splat(-u00.y); GS[tid][5] = splat(-u01.y);
        GS[tid][6] = splat(-u01.x); GS[tid][7] = 0ull;
        GP[tid][0] = pk(u00.x, -u01.x);  GP[tid][1] = pk(u01.x, u00.x);
        GP[tid][2] = pk(u00.y, u01.y);   GP[tid][3] = pk(u01.y, -u00.y);
        GP[tid][4] = pk(-u00.y, -u01.y); GP[tid][5] = pk(-u01.y, u00.y);
        const float tc = angles[layer * 48 + 36 + wire];
        const float c = cosf(0.5f*tc), s = sinf(0.5f*tc);
        CC[tid][0] = pk(c, c); CC[tid][1] = pk(s, s); CC[tid][2] = pk(-s, -s);
        CL[tid][0] = pk(1.f, c); CL[tid][1] = pk(0.f, s); CL[tid][2] = pk(0.f, -s);
    } else if (tid >= 32 && tid < 39) {
        // FGS: layer0 (wire, slot): (1,0)(2,1)(4,3)(5,4)(7,6)(8,7)(10,9)
        const int f = tid - 32;
        const int wires[7] = {1,2,4,5,7,8,10};
        const int slots[7] = {0,1,3,4,6,7,9};
        Cx u00, u01, v00, v01;
        fused_u(angles, 0, wires[f], u00, u01);
        const float th = angles[36 + slots[f]];
        rx_compose(u00, u01, cosf(0.5f*th), sinf(0.5f*th), v00, v01);
        FGS[f][0] = splat(v00.x);  FGS[f][1] = splat(v01.x);
        FGS[f][2] = splat(v00.y);  FGS[f][3] = splat(v01.y);
        FGS[f][4] = splat(-v00.y); FGS[f][5] = splat(-v01.y);
        FGS[f][6] = splat(-v01.x); FGS[f][7] = 0ull;
    } else if (tid >= 40 && tid < 44) {
        // FGP: layer0 (wire, slot): (3,2)(6,5)(9,8)(11,10)
        const int f = tid - 40;
        const int wires[4] = {3,6,9,11};
        const int slots[4] = {2,5,8,10};
        Cx u00, u01, v00, v01;
        fused_u(angles, 0, wires[f], u00, u01);
        const float th = angles[36 + slots[f]];
        rx_compose(u00, u01, cosf(0.5f*th), sinf(0.5f*th), v00, v01);
        FGP[f][0] = pk(v00.x, -v01.x);  FGP[f][1] = pk(v01.x, v00.x);
        FGP[f][2] = pk(v00.y, v01.y);   FGP[f][3] = pk(v01.y, -v00.y);
        FGP[f][4] = pk(-v00.y, -v01.y); FGP[f][5] = pk(-v01.y, v00.y);
    } else if (tid == 44) {
        // LPQ: lane lo = U(L1,w0), lane hi = RX(angles[84]) * U
        Cx u00, u01, v00, v01;
        fused_u(angles, 1, 0, u00, u01);
        const float th = angles[84];
        rx_compose(u00, u01, cosf(0.5f*th), sinf(0.5f*th), v00, v01);
        LPQ[0] = pk(u00.x, v00.x);   LPQ[1] = pk(u01.x, v01.x);
        LPQ[2] = pk(u00.y, v00.y);   LPQ[3] = pk(u01.y, v01.y);
        LPQ[4] = pk(-u00.y, -v00.y); LPQ[5] = pk(-u01.y, -v01.y);
        LPQ[6] = pk(-u01.x, -v01.x); LPQ[7] = 0ull;
    }
    if (tid < NFEAT) feats[tid] = 0.0f;
    __syncthreads();

    u64 R[8], I[8];

    // ---- P1: S={8,9,10,11} (packed=8); gmem load; 1q w0; fused w1,w2,w3 with CRX 0,1,2 ----
    {
        const float* in = sv + (size_t)bidx * DIM;
#pragma unroll
        for (int m = 0; m < 8; m++) {
            R[m] = pk(in[((2*m) << 8) | tid], in[((2*m+1) << 8) | tid]);
            I[m] = 0ull;
        }
        v1q_real<3>(R, I, GS[0]);           // w0 (b11), state real
        c1q<3,2>(R, I, GS[1], FGS[0]);      // w1 (b10) + CRX(0,1)
        c1q<2,1>(R, I, GS[2], FGS[1]);      // w2 (b9)  + CRX(1,2)
        cv2q<1>(R, I, GP[3], FGP[0]);       // w3 (b8 packed) + CRX(2,3)
        vst<8,9,10,11>(R, I, cx, swzc(tid));
    }
    __syncthreads();

    // ---- P2: S={5,6,7,8} (packed=5); fused w4,w5,w6 with CRX 3,4,5 ----
    {
        const int pb = swzc(mkbase<0,1,2,3,4, 9,10,11>(tid));
        vld<5,6,7,8>(R, I, cx, pb);
        c1q<3,2>(R, I, GS[4], FGS[2]);      // w4 (b7) + CRX(3,4)
        c1q<2,1>(R, I, GS[5], FGS[3]);      // w5 (b6) + CRX(4,5)
        cv2q<1>(R, I, GP[6], FGP[1]);       // w6 (b5 packed) + CRX(5,6)
        vst<5,6,7,8>(R, I, cx, pb);
    }
    __syncthreads();

    // ---- P3: S={2,3,4,5} (packed=2); fused w7,w8,w9 with CRX 6,7,8 ----
    {
        const int pb = swzc(mkbase<0,1,7,8,9, 6,10,11>(tid));
        vld<2,3,4,5>(R, I, cx, pb);
        c1q<3,2>(R, I, GS[7], FGS[4]);      // w7 (b4) + CRX(6,7)
        c1q<2,1>(R, I, GS[8], FGS[5]);      // w8 (b3) + CRX(7,8)
        cv2q<1>(R, I, GP[9], FGP[2]);       // w9 (b2 packed) + CRX(8,9)
        vst<2,3,4,5>(R, I, cx, pb);
    }
    __syncthreads();

    // ---- P4 (mega): S={0,1,2,11} (packed=0) ----
    {
        const int pb = swzc(mkbase<5,6,7,3,4, 8,9,10>(tid));
        vld<0,1,2,11>(R, I, cx, pb);
        c1q<2,1>(R, I, GS[10], FGS[6]);     // L0 w10 (b1) + CRX(9,10)
        cv2q<1>(R, I, GP[11], FGP[3]);      // L0 w11 (b0 packed) + CRX(10,11)
        vcrx0c<3>(R, I, CL[11]);            // L0 CRX(11,0): ctrl packed, tgt b11
        v2q(R, I, GP[23]);                  // L1 w11 (b0 packed)
        v1q<1>(R, I, GS[22]);               // L1 w10 (b1)
        v1q<2>(R, I, GS[21]);               // L1 w9  (b2)
        v1q<3>(R, I, LPQ);                  // L1 w0 (b11) + L1 CRX(11,0) [ctrl = packed lane]
        vcrx0t<1>(R, I, CC[13]);            // L1 CRX(10,11): ctrl b1, tgt packed
        vcrx<2,1>(R, I, CC[14]);            // L1 CRX(9,10)
        vst<0,1,2,11>(R, I, cx, pb);
    }
    __syncthreads();

    // ---- P5: S={2,3,4,5}; L1 1q w8,w7,w6; CRX 15,16,17 ----
    {
        const int pb = swzc(mkbase<0,1,7,8,9, 6,10,11>(tid));
        vld<2,3,4,5>(R, I, cx, pb);
        v1q<1>(R, I, GS[20]);
        v1q<2>(R, I, GS[19]);
        v1q<3>(R, I, GS[18]);
        vcrx0t<1>(R, I, CC[15]);    // CRX(8,9): bits(3,2)
        vcrx<2,1>(R, I, CC[16]);    // CRX(7,8): bits(4,3)
        vcrx<3,2>(R, I, CC[17]);    // CRX(6,7): bits(5,4)
        vst<2,3,4,5>(R, I, cx, pb);
    }
    __syncthreads();

    // ---- P6: S={5,6,7,8}; L1 1q w5,w4,w3; CRX 18,19,20 ----
    {
        const int pb = swzc(mkbase<0,1,2,3,4, 9,10,11>(tid));
        vld<5,6,7,8>(R, I, cx, pb);
        v1q<1>(R, I, GS[17]);
        v1q<2>(R, I, GS[16]);
        v1q<3>(R, I, GS[15]);
        vcrx0t<1>(R, I, CC[18]);    // CRX(5,6): bits(6,5)
        vcrx<2,1>(R, I, CC[19]);    // CRX(4,5): bits(7,6)
        vcrx<3,2>(R, I, CC[20]);    // CRX(3,4): bits(8,7)
        vst<5,6,7,8>(R, I, cx, pb);
    }
    __syncthreads();

    // ---- P7: S={8,9,10,11}; L1 1q w2,w1; CRX 21,22,23; + Z expvals + X/Y q0-3 ----
    {
        const int pb = swzc(tid);
        vld<8,9,10,11>(R, I, cx, pb);
        v1q<1>(R, I, GS[14]);       // w2 (b9)
        v1q<2>(R, I, GS[13]);       // w1 (b10)
        vcrx0t<1>(R, I, CC[21]);    // CRX(2,3): bits(9,8)
        vcrx<2,1>(R, I, CC[22]);    // CRX(1,2): bits(10,9)
        vcrx<3,2>(R, I, CC[23]);    // CRX(0,1): bits(11,10)
        vst<8,9,10,11>(R, I, cx, pb);

        u64 tot2 = 0ull, d1v = 0ull, d2v = 0ull, d3v = 0ull;
#pragma unroll
        for (int m = 0; m < 8; m++) {
            const u64 p2 = f2fma(R[m], R[m], f2mul(I[m], I[m]));
            tot2 = f2add(tot2, p2);
            if (m & 1) d1v = f2add(d1v, p2);
            if (m & 2) d2v = f2add(d2v, p2);
            if (m & 4) d3v = f2add(d3v, p2);
        }
        float tlo, thi; upk(tot2, tlo, thi);
        const float tot = tlo + thi;
        const float d0 = thi;
        float a, b;
        upk(d1v, a, b); const float d1 = a + b;
        upk(d2v, a, b); const float d2 = a + b;
        upk(d3v, a, b); const float d3 = a + b;
        red_add(tot - 2.f*d0, &feats[24 + 3]);
        red_add(tot - 2.f*d1, &feats[24 + 2]);
        red_add(tot - 2.f*d2, &feats[24 + 1]);
        red_add(tot - 2.f*d3, &feats[24 + 0]);
#pragma unroll
        for (int fb = 0; fb < 8; fb++) {
            const float s = ((tid >> fb) & 1) ? -tot : tot;
            red_add(s, &feats[24 + (11 - fb)]);
        }
        vcross0(R, I, feats, 3);
        vcross<1>(R, I, feats, 2);
        vcross<2>(R, I, feats, 1);
        vcross<3>(R, I, feats, 0);
    }
    __syncthreads();

    // ---- P8: S={4,5,6,7}: X/Y qubits 7,6,5,4 ----
    {
        const int pb = swzc(mkbase<0,1,2,3,9, 8,10,11>(tid));
        vld<4,5,6,7>(R, I, cx, pb);
        vcross0(R, I, feats, 7);
        vcross<1>(R, I, feats, 6);
        vcross<2>(R, I, feats, 5);
        vcross<3>(R, I, feats, 4);
    }

    // ---- P9: S={0,1,2,3}: X/Y qubits 11,10,9,8 ----
    {
        const int pb = swzc(mkbase<5,6,7,8,4, 9,10,11>(tid));
        vld<0,1,2,3>(R, I, cx, pb);
        vcross0(R, I, feats, 11);
        vcross<1>(R, I, feats, 10);
        vcross<2>(R, I, feats, 9);
        vcross<3>(R, I, feats, 8);
    }
    __syncthreads();

    // ---- Linear head ----
    if (tid < NCLASSES) {
        float acc = bv[tid];
#pragma unroll
        for (int j = 0; j < NFEAT; ++j)
            acc += Wm[tid * NFEAT + j] * feats[j];
        out[(size_t)bidx * NCLASSES + tid] = acc;
    }
}

extern "C" void kernel_launch(void* const* d_in, const int* in_sizes, int n_in,
                              void* d_out, int out_size)
{
    const float* sv     = (const float*)d_in[0];  // [2048, 4096]
    const float* angles = (const float*)d_in[1];  // [96]
    const float* Wm     = (const float*)d_in[2];  // [10, 36]
    const float* bv     = (const float*)d_in[3];  // [10]
    float* out          = (float*)d_out;          // [2048, 10]
    (void)in_sizes; (void)n_in; (void)out_size;

    qsim_kernel<<<2048, THREADS>>>(sv, angles, Wm, bv, out);
}

// round 10
// speedup vs baseline: 1.3676x; 1.3676x over previous
#include <cuda_runtime.h>

#define NQ       12
#define DIM      4096
#define THREADS  256
#define NCLASSES 10
#define NFEAT    36

typedef unsigned long long u64;

struct Cx { float x, y; };
__device__ __forceinline__ Cx cmul(Cx a, Cx b) {
    return Cx{a.x * b.x - a.y * b.y, a.x * b.y + a.y * b.x};
}

// ---- f32x2 helpers ----
__device__ __forceinline__ u64 pk(float lo, float hi) {
    u64 r; asm("mov.b64 %0, {%1,%2};" : "=l"(r) : "f"(lo), "f"(hi)); return r;
}
__device__ __forceinline__ void upk(u64 v, float& lo, float& hi) {
    asm("mov.b64 {%0,%1}, %2;" : "=f"(lo), "=f"(hi) : "l"(v));
}
__device__ __forceinline__ u64 f2fma(u64 a, u64 b, u64 c) {
    u64 r; asm("fma.rn.f32x2 %0, %1, %2, %3;" : "=l"(r) : "l"(a), "l"(b), "l"(c)); return r;
}
__device__ __forceinline__ u64 f2mul(u64 a, u64 b) {
    u64 r; asm("mul.rn.f32x2 %0, %1, %2;" : "=l"(r) : "l"(a), "l"(b)); return r;
}
__device__ __forceinline__ u64 f2add(u64 a, u64 b) {
    u64 r; asm("add.rn.f32x2 %0, %1, %2;" : "=l"(r) : "l"(a), "l"(b)); return r;
}
__device__ __forceinline__ u64 f2sub(u64 a, u64 b) {
    u64 r; asm("sub.rn.f32x2 %0, %1, %2;" : "=l"(r) : "l"(a), "l"(b)); return r;
}
__device__ __forceinline__ u64 splat(float x) { return pk(x, x); }

// ---- addressing ----
__device__ __forceinline__ int swzc(int i) { return i ^ ((i >> 5) & 31); }

template<int S0,int S1,int S2,int S3>
__device__ __forceinline__ int offj(int j) {
    return ((j & 1) << S0) | (((j >> 1) & 1) << S1) | (((j >> 2) & 1) << S2) | (((j >> 3) & 1) << S3);
}
template<int L0,int L1,int L2,int L3,int L4,int W0,int W1,int W2>
__device__ __forceinline__ int mkbase(int t) {
    return ((t & 1) << L0) | (((t >> 1) & 1) << L1) | (((t >> 2) & 1) << L2) |
           (((t >> 3) & 1) << L3) | (((t >> 4) & 1) << L4) |
           (((t >> 5) & 1) << W0) | (((t >> 6) & 1) << W1) | (((t >> 7) & 1) << W2);
}

// Each u64 in re2/im2 packs {batch0, batch1} of one amplitude.
template<int S0,int S1,int S2,int S3>
__device__ __forceinline__ void vld(u64 R[16], u64 I[16], const u64* re2, const u64* im2, int pb) {
#pragma unroll
    for (int j = 0; j < 16; j++) {
        const int ad = pb ^ swzc(offj<S0,S1,S2,S3>(j));
        R[j] = re2[ad]; I[j] = im2[ad];
    }
}
template<int S0,int S1,int S2,int S3>
__device__ __forceinline__ void vst(const u64 R[16], const u64 I[16], u64* re2, u64* im2, int pb) {
#pragma unroll
    for (int j = 0; j < 16; j++) {
        const int ad = pb ^ swzc(offj<S0,S1,S2,S3>(j));
        re2[ad] = R[j]; im2[ad] = I[j];
    }
}

// ---- gates (uniform over both lanes = both batches) ----
// SU(2): U = [[u00,u01],[-u01*,u00*]]
// GS: [0]=u00x [1]=u01x [2]=u00y [3]=u01y [4]=-u00y [5]=-u01y [6]=-u01x
template<int K>
__device__ __forceinline__ void v1q(u64 R[16], u64 I[16], const u64* g) {
    const u64 g0 = g[0], g1 = g[1], g2 = g[2], g3 = g[3], g4 = g[4], g5 = g[5], g6 = g[6];
#pragma unroll
    for (int j = 0; j < 16; j++) {
        if (!((j >> K) & 1)) {
            const int j1 = j | (1 << K);
            const u64 a = R[j], ai = I[j], b = R[j1], bi = I[j1];
            R[j]  = f2fma(g0, a, f2fma(g4, ai, f2fma(g1, b, f2mul(g5, bi))));
            I[j]  = f2fma(g2, a, f2fma(g0, ai, f2fma(g3, b, f2mul(g1, bi))));
            R[j1] = f2fma(g6, a, f2fma(g5, ai, f2fma(g0, b, f2mul(g2, bi))));
            I[j1] = f2fma(g3, a, f2fma(g6, ai, f2fma(g4, b, f2mul(g0, bi))));
        }
    }
}
template<int K>  // first gate on purely real state (I == 0)
__device__ __forceinline__ void v1q_real(u64 R[16], u64 I[16], const u64* g) {
    const u64 g0 = g[0], g1 = g[1], g2 = g[2], g3 = g[3], g4 = g[4], g6 = g[6];
#pragma unroll
    for (int j = 0; j < 16; j++) {
        if (!((j >> K) & 1)) {
            const int j1 = j | (1 << K);
            const u64 a = R[j], b = R[j1];
            R[j]  = f2fma(g0, a, f2mul(g1, b));
            I[j]  = f2fma(g2, a, f2mul(g3, b));
            R[j1] = f2fma(g6, a, f2mul(g0, b));
            I[j1] = f2fma(g3, a, f2mul(g4, b));
        }
    }
}
// CRX: q[0]={c,c} q[1]={s,s} q[2]={-s,-s}
template<int KC,int KT>
__device__ __forceinline__ void vcrx(u64 R[16], u64 I[16], const u64* q) {
    const u64 q0 = q[0], q1 = q[1], q2 = q[2];
#pragma unroll
    for (int j = 0; j < 16; j++) {
        if (((j >> KC) & 1) && !((j >> KT) & 1)) {
            const int j1 = j | (1 << KT);
            const u64 a = R[j], ai = I[j], b = R[j1], bi = I[j1];
            R[j]  = f2fma(q0, a,  f2mul(q1, bi));
            I[j]  = f2fma(q0, ai, f2mul(q2, b));
            R[j1] = f2fma(q0, b,  f2mul(q1, ai));
            I[j1] = f2fma(q0, bi, f2mul(q2, a));
        }
    }
}

// Packed reduction: reduce u64 (2 batches) across warp, lane0 atomics both halves.
__device__ __forceinline__ void red_add2(u64 v, float* d0, float* d1) {
#pragma unroll
    for (int o = 16; o > 0; o >>= 1)
        v = f2add(v, __shfl_xor_sync(0xffffffffu, v, o));
    if ((threadIdx.x & 31) == 0) {
        float a, b; upk(v, a, b);
        atomicAdd(d0, a);
        atomicAdd(d1, b);
    }
}

// <X>,<Y> across local bit K (both batches at once)
template<int K>
__device__ __forceinline__ void vcross(const u64 R[16], const u64 I[16],
                                       float* feats0, float* feats1, int q) {
    u64 cr2 = 0ull, cip = 0ull, cin = 0ull;
#pragma unroll
    for (int j = 0; j < 16; j++) {
        if (!((j >> K) & 1)) {
            const int j1 = j | (1 << K);
            cr2 = f2fma(R[j], R[j1], f2fma(I[j], I[j1], cr2));
            cip = f2fma(R[j], I[j1], cip);
            cin = f2fma(I[j], R[j1], cin);
        }
    }
    const u64 crd = f2add(cr2, cr2);                 // 2*cr
    const u64 cid0 = f2sub(cip, cin);
    const u64 cid = f2add(cid0, cid0);               // 2*ci
    red_add2(crd, &feats0[q], &feats1[q]);
    red_add2(cid, &feats0[NQ + q], &feats1[NQ + q]);
}

__global__ __launch_bounds__(THREADS, 2)
void qsim_kernel(const float* __restrict__ sv,
                 const float* __restrict__ angles,
                 const float* __restrict__ Wm,
                 const float* __restrict__ bv,
                 float* __restrict__ out)
{
    extern __shared__ u64 smem_state[];     // re2[4096] ++ im2[4096]  (64 KB)
    u64* re2 = smem_state;
    u64* im2 = smem_state + DIM;

    __shared__ u64 GS[24][8];   // SU(2)-compressed fused 1q coefs (7 used)
    __shared__ u64 CC[24][3];
    __shared__ float feats[2][NFEAT];

    const int tid  = threadIdx.x;
    const int bidx = blockIdx.x;

    if (tid < 24) {
        const int layer = tid / NQ;
        const int wire  = tid % NQ;
        const int base  = layer * 48;
        const float tx = angles[base + wire];
        const float ty = angles[base + 12 + wire];
        const float tz = angles[base + 24 + wire];
        const float cxv = cosf(0.5f*tx), sxv = sinf(0.5f*tx);
        const float cyv = cosf(0.5f*ty), syv = sinf(0.5f*ty);
        const float czv = cosf(0.5f*tz), szv = sinf(0.5f*tz);
        Cx m00{cyv*cxv,  syv*sxv};
        Cx m01{-syv*cxv, -cyv*sxv};
        Cx ezm{czv, -szv};
        Cx u00 = cmul(ezm, m00), u01 = cmul(ezm, m01);
        GS[tid][0] = splat(u00.x);  GS[tid][1] = splat(u01.x);
        GS[tid][2] = splat(u00.y);  GS[tid][3] = splat(u01.y);
        GS[tid][4] = splat(-u00.y); GS[tid][5] = splat(-u01.y);
        GS[tid][6] = splat(-u01.x); GS[tid][7] = 0ull;
        const float tc = angles[base + 36 + wire];
        const float c = cosf(0.5f*tc), s = sinf(0.5f*tc);
        CC[tid][0] = pk(c, c); CC[tid][1] = pk(s, s); CC[tid][2] = pk(-s, -s);
    }
    if (tid < 2 * NFEAT) feats[0][tid] = 0.0f;   // feats contiguous [2][36]
    __syncthreads();

    u64 R[16], I[16];

    // ---- P1: S={8,9,10,11} (wires 3,2,1,0); gmem load; L0 1q; CRX 0,1,2 ----
    {
        const float* in0 = sv + ((size_t)(2 * bidx))     * DIM;
        const float* in1 = sv + ((size_t)(2 * bidx) + 1) * DIM;
#pragma unroll
        for (int j = 0; j < 16; j++) {
            const int idx = (j << 8) | tid;
            R[j] = pk(in0[idx], in1[idx]);
            I[j] = 0ull;
        }
        v1q_real<0>(R, I, GS[3]);   // wire3 (bit8), state real
        v1q<1>(R, I, GS[2]);
        v1q<2>(R, I, GS[1]);
        v1q<3>(R, I, GS[0]);
        vcrx<3,2>(R, I, CC[0]);     // CRX(0,1)
        vcrx<2,1>(R, I, CC[1]);     // CRX(1,2)
        vcrx<1,0>(R, I, CC[2]);     // CRX(2,3)
        vst<8,9,10,11>(R, I, re2, im2, swzc(tid));
    }
    __syncthreads();

    // ---- P2: S={5,6,7,8} (wires 6,5,4,3); L0 1q 6,5,4; CRX 3,4,5 ----
    {
        const int pb = swzc(mkbase<0,1,2,3,4, 9,10,11>(tid));
        vld<5,6,7,8>(R, I, re2, im2, pb);
        v1q<0>(R, I, GS[6]);
        v1q<1>(R, I, GS[5]);
        v1q<2>(R, I, GS[4]);
        vcrx<3,2>(R, I, CC[3]);
        vcrx<2,1>(R, I, CC[4]);
        vcrx<1,0>(R, I, CC[5]);
        vst<5,6,7,8>(R, I, re2, im2, pb);
    }
    __syncthreads();

    // ---- P3: S={2,3,4,5} (wires 9,8,7,6); L0 1q 9,8,7; CRX 6,7,8 ----
    {
        const int pb = swzc(mkbase<0,1,7,8,9, 6,10,11>(tid));
        vld<2,3,4,5>(R, I, re2, im2, pb);
        v1q<0>(R, I, GS[9]);
        v1q<1>(R, I, GS[8]);
        v1q<2>(R, I, GS[7]);
        vcrx<3,2>(R, I, CC[6]);
        vcrx<2,1>(R, I, CC[7]);
        vcrx<1,0>(R, I, CC[8]);
        vst<2,3,4,5>(R, I, re2, im2, pb);
    }
    __syncthreads();

    // ---- P4 (mega): S={0,1,2,11} (wires 11,10,9,0); + X/Y q11,q10 (bits 0,1 final) ----
    {
        const int pb = swzc(mkbase<5,6,7,3,4, 8,9,10>(tid));
        vld<0,1,2,11>(R, I, re2, im2, pb);
        v1q<0>(R, I, GS[11]);       // L0 wire11
        v1q<1>(R, I, GS[10]);       // L0 wire10
        vcrx<2,1>(R, I, CC[9]);     // CRX(9,10)
        vcrx<1,0>(R, I, CC[10]);    // CRX(10,11)
        vcrx<0,3>(R, I, CC[11]);    // CRX(11,0)
        v1q<0>(R, I, GS[23]);       // L1 wire11
        v1q<1>(R, I, GS[22]);       // L1 wire10
        v1q<2>(R, I, GS[21]);       // L1 wire9
        v1q<3>(R, I, GS[12]);       // L1 wire0
        vcrx<0,3>(R, I, CC[12]);    // L1 CRX(11,0)
        vcrx<1,0>(R, I, CC[13]);    // L1 CRX(10,11)
        vcrx<2,1>(R, I, CC[14]);    // L1 CRX(9,10)
        vst<0,1,2,11>(R, I, re2, im2, pb);
        // bits 0,1 untouched by P5-P7 -> expvals final now
        vcross<0>(R, I, feats[0], feats[1], 11);   // idx bit0 -> qubit 11
        vcross<1>(R, I, feats[0], feats[1], 10);   // idx bit1 -> qubit 10
    }
    __syncthreads();

    // ---- P5: S={2,3,4,5}; L1 1q 8,7,6; CRX 15,16,17; + X/Y q9,q8,q7 (bits 2,3,4 final) ----
    {
        const int pb = swzc(mkbase<0,1,7,8,9, 6,10,11>(tid));
        vld<2,3,4,5>(R, I, re2, im2, pb);
        v1q<1>(R, I, GS[20]);
        v1q<2>(R, I, GS[19]);
        v1q<3>(R, I, GS[18]);
        vcrx<1,0>(R, I, CC[15]);    // CRX(8,9): bits(3,2)
        vcrx<2,1>(R, I, CC[16]);    // CRX(7,8): bits(4,3)
        vcrx<3,2>(R, I, CC[17]);    // CRX(6,7): bits(5,4)
        vst<2,3,4,5>(R, I, re2, im2, pb);
        vcross<0>(R, I, feats[0], feats[1], 9);    // bit2 -> q9
        vcross<1>(R, I, feats[0], feats[1], 8);    // bit3 -> q8
        vcross<2>(R, I, feats[0], feats[1], 7);    // bit4 -> q7
    }
    __syncthreads();

    // ---- P6: S={5,6,7,8}; L1 1q 5,4,3; CRX 18,19,20; + X/Y q6,q5,q4 (bits 5,6,7 final) ----
    {
        const int pb = swzc(mkbase<0,1,2,3,4, 9,10,11>(tid));
        vld<5,6,7,8>(R, I, re2, im2, pb);
        v1q<1>(R, I, GS[17]);
        v1q<2>(R, I, GS[16]);
        v1q<3>(R, I, GS[15]);
        vcrx<1,0>(R, I, CC[18]);    // CRX(5,6): bits(6,5)
        vcrx<2,1>(R, I, CC[19]);    // CRX(4,5): bits(7,6)
        vcrx<3,2>(R, I, CC[20]);    // CRX(3,4): bits(8,7)
        vst<5,6,7,8>(R, I, re2, im2, pb);
        vcross<0>(R, I, feats[0], feats[1], 6);    // bit5 -> q6
        vcross<1>(R, I, feats[0], feats[1], 5);    // bit6 -> q5
        vcross<2>(R, I, feats[0], feats[1], 4);    // bit7 -> q4
    }
    __syncthreads();

    // ---- P7: S={8,9,10,11}; L1 1q 2,1; CRX 21,22,23; all Z + X/Y q3..q0. NO store. ----
    {
        const int pb = swzc(tid);
        vld<8,9,10,11>(R, I, re2, im2, pb);
        v1q<1>(R, I, GS[14]);       // wire2
        v1q<2>(R, I, GS[13]);       // wire1
        vcrx<1,0>(R, I, CC[21]);    // CRX(2,3)
        vcrx<2,1>(R, I, CC[22]);    // CRX(1,2)
        vcrx<3,2>(R, I, CC[23]);    // CRX(0,1)

        // |amp|^2 sums (packed per batch)
        u64 tot2 = 0ull, d0v = 0ull, d1v = 0ull, d2v = 0ull, d3v = 0ull;
#pragma unroll
        for (int j = 0; j < 16; j++) {
            const u64 p2 = f2fma(R[j], R[j], f2mul(I[j], I[j]));
            tot2 = f2add(tot2, p2);
            if (j & 1) d0v = f2add(d0v, p2);
            if (j & 2) d1v = f2add(d1v, p2);
            if (j & 4) d2v = f2add(d2v, p2);
            if (j & 8) d3v = f2add(d3v, p2);
        }
        // Z for tile bits 8..11 -> qubits 3..0 : z = tot - 2*d  (per-thread, linear)
        red_add2(f2sub(tot2, f2add(d0v, d0v)), &feats[0][24+3], &feats[1][24+3]);
        red_add2(f2sub(tot2, f2add(d1v, d1v)), &feats[0][24+2], &feats[1][24+2]);
        red_add2(f2sub(tot2, f2add(d2v, d2v)), &feats[0][24+1], &feats[1][24+1]);
        red_add2(f2sub(tot2, f2add(d3v, d3v)), &feats[0][24+0], &feats[1][24+0]);

        // Z for free bits via 5-stage Walsh-Hadamard butterfly over the warp.
        // After WHT, lane L holds sum_t (-1)^{popcnt(L&t)} tot_t over the warp.
        // Lane 2^fb = signed sum for lane-bit fb (fb=0..4); lane 0 = plain warp total.
        {
            u64 x = tot2;
#pragma unroll
            for (int m = 1; m <= 16; m <<= 1) {
                const u64 y = __shfl_xor_sync(0xffffffffu, x, m);
                x = (tid & m) ? f2sub(y, x) : f2add(x, y);
            }
            const int lane = tid & 31;
            float a, b;
            if (lane == 1)  { upk(x, a, b); atomicAdd(&feats[0][24+11], a); atomicAdd(&feats[1][24+11], b); } // fb0 -> q11
            if (lane == 2)  { upk(x, a, b); atomicAdd(&feats[0][24+10], a); atomicAdd(&feats[1][24+10], b); } // fb1 -> q10
            if (lane == 4)  { upk(x, a, b); atomicAdd(&feats[0][24+9],  a); atomicAdd(&feats[1][24+9],  b); } // fb2 -> q9
            if (lane == 8)  { upk(x, a, b); atomicAdd(&feats[0][24+8],  a); atomicAdd(&feats[1][24+8],  b); } // fb3 -> q8
            if (lane == 16) { upk(x, a, b); atomicAdd(&feats[0][24+7],  a); atomicAdd(&feats[1][24+7],  b); } // fb4 -> q7
            if (lane == 0) {
                upk(x, a, b);  // warp total, both batches
#pragma unroll
                for (int fb = 5; fb < 8; fb++) {     // warp-uniform sign bits -> q6,q5,q4
                    const float s = ((tid >> fb) & 1) ? -1.f : 1.f;
                    atomicAdd(&feats[0][24 + (11 - fb)], s * a);
                    atomicAdd(&feats[1][24 + (11 - fb)], s * b);
                }
            }
        }

        // X/Y for tile bits 8..11 -> qubits 3..0
        vcross<0>(R, I, feats[0], feats[1], 3);
        vcross<1>(R, I, feats[0], feats[1], 2);
        vcross<2>(R, I, feats[0], feats[1], 1);
        vcross<3>(R, I, feats[0], feats[1], 0);
    }
    __syncthreads();

    // ---- Linear head: 2 batches x 10 classes ----
    if (tid < 2 * NCLASSES) {
        const int batch = tid / NCLASSES;
        const int c     = tid % NCLASSES;
        float acc = bv[c];
#pragma unroll
        for (int j = 0; j < NFEAT; ++j)
            acc += Wm[c * NFEAT + j] * feats[batch][j];
        out[((size_t)(2 * bidx) + batch) * NCLASSES + c] = acc;
    }
}

extern "C" void kernel_launch(void* const* d_in, const int* in_sizes, int n_in,
                              void* d_out, int out_size)
{
    const float* sv     = (const float*)d_in[0];  // [2048, 4096]
    const float* angles = (const float*)d_in[1];  // [96]
    const float* Wm     = (const float*)d_in[2];  // [10, 36]
    const float* bv     = (const float*)d_in[3];  // [10]
    float* out          = (float*)d_out;          // [2048, 10]
    (void)in_sizes; (void)n_in; (void)out_size;

    const int smem_bytes = 2 * DIM * (int)sizeof(u64);  // 64 KB dynamic
    cudaFuncSetAttribute(qsim_kernel, cudaFuncAttributeMaxDynamicSharedMemorySize, smem_bytes);
    qsim_kernel<<<1024, THREADS, smem_bytes>>>(sv, angles, Wm, bv, out);
}

// round 11
// speedup vs baseline: 1.3910x; 1.0171x over previous
#include <cuda_runtime.h>

#define NQ       12
#define DIM      4096
#define THREADS  256
#define NCLASSES 10
#define NFEAT    36

typedef unsigned long long u64;

struct Cx { float x, y; };
__device__ __forceinline__ Cx cmul(Cx a, Cx b) {
    return Cx{a.x * b.x - a.y * b.y, a.x * b.y + a.y * b.x};
}

// ---- f32x2 helpers ----
__device__ __forceinline__ u64 pk(float lo, float hi) {
    u64 r; asm("mov.b64 %0, {%1,%2};" : "=l"(r) : "f"(lo), "f"(hi)); return r;
}
__device__ __forceinline__ void upk(u64 v, float& lo, float& hi) {
    asm("mov.b64 {%0,%1}, %2;" : "=f"(lo), "=f"(hi) : "l"(v));
}
__device__ __forceinline__ u64 f2fma(u64 a, u64 b, u64 c) {
    u64 r; asm("fma.rn.f32x2 %0, %1, %2, %3;" : "=l"(r) : "l"(a), "l"(b), "l"(c)); return r;
}
__device__ __forceinline__ u64 f2mul(u64 a, u64 b) {
    u64 r; asm("mul.rn.f32x2 %0, %1, %2;" : "=l"(r) : "l"(a), "l"(b)); return r;
}
__device__ __forceinline__ u64 f2add(u64 a, u64 b) {
    u64 r; asm("add.rn.f32x2 %0, %1, %2;" : "=l"(r) : "l"(a), "l"(b)); return r;
}
__device__ __forceinline__ u64 f2sub(u64 a, u64 b) {
    u64 r; asm("sub.rn.f32x2 %0, %1, %2;" : "=l"(r) : "l"(a), "l"(b)); return r;
}
__device__ __forceinline__ u64 splat(float x) { return pk(x, x); }

// ---- addressing ----
__device__ __forceinline__ int swzc(int i) { return i ^ ((i >> 5) & 31); }

template<int S0,int S1,int S2,int S3>
__device__ __forceinline__ int offj(int j) {
    return ((j & 1) << S0) | (((j >> 1) & 1) << S1) | (((j >> 2) & 1) << S2) | (((j >> 3) & 1) << S3);
}
template<int L0,int L1,int L2,int L3,int L4,int W0,int W1,int W2>
__device__ __forceinline__ int mkbase(int t) {
    return ((t & 1) << L0) | (((t >> 1) & 1) << L1) | (((t >> 2) & 1) << L2) |
           (((t >> 3) & 1) << L3) | (((t >> 4) & 1) << L4) |
           (((t >> 5) & 1) << W0) | (((t >> 6) & 1) << W1) | (((t >> 7) & 1) << W2);
}

// Each u64 in re2/im2 packs {batch0, batch1} of one amplitude.
template<int S0,int S1,int S2,int S3>
__device__ __forceinline__ void vld(u64 R[16], u64 I[16], const u64* re2, const u64* im2, int pb) {
#pragma unroll
    for (int j = 0; j < 16; j++) {
        const int ad = pb ^ swzc(offj<S0,S1,S2,S3>(j));
        R[j] = re2[ad]; I[j] = im2[ad];
    }
}
template<int S0,int S1,int S2,int S3>
__device__ __forceinline__ void vst(const u64 R[16], const u64 I[16], u64* re2, u64* im2, int pb) {
#pragma unroll
    for (int j = 0; j < 16; j++) {
        const int ad = pb ^ swzc(offj<S0,S1,S2,S3>(j));
        re2[ad] = R[j]; im2[ad] = I[j];
    }
}

// ---- gates ----
// SU(2): U = [[u00,u01],[-u01*,u00*]]
// GS: [0]=u00x [1]=u01x [2]=u00y [3]=u01y [4]=-u00y [5]=-u01y [6]=-u01x
#define V1Q_BODY(jlo, jhi) do {                                                  \
    const u64 a = R[jlo], ai = I[jlo], b = R[jhi], bi = I[jhi];                  \
    R[jlo] = f2fma(g0, a, f2fma(g4, ai, f2fma(g1, b, f2mul(g5, bi))));           \
    I[jlo] = f2fma(g2, a, f2fma(g0, ai, f2fma(g3, b, f2mul(g1, bi))));           \
    R[jhi] = f2fma(g6, a, f2fma(g5, ai, f2fma(g0, b, f2mul(g2, bi))));           \
    I[jhi] = f2fma(g3, a, f2fma(g6, ai, f2fma(g4, b, f2mul(g0, bi))));           \
} while (0)

template<int K>
__device__ __forceinline__ void v1q(u64 R[16], u64 I[16], const u64* g) {
    const u64 g0 = g[0], g1 = g[1], g2 = g[2], g3 = g[3], g4 = g[4], g5 = g[5], g6 = g[6];
#pragma unroll
    for (int j = 0; j < 16; j++) {
        if (!((j >> K) & 1)) { const int j1 = j | (1 << K); V1Q_BODY(j, j1); }
    }
}
template<int K>  // first gate on purely real state (I == 0)
__device__ __forceinline__ void v1q_real(u64 R[16], u64 I[16], const u64* g) {
    const u64 g0 = g[0], g1 = g[1], g2 = g[2], g3 = g[3], g4 = g[4], g6 = g[6];
#pragma unroll
    for (int j = 0; j < 16; j++) {
        if (!((j >> K) & 1)) {
            const int j1 = j | (1 << K);
            const u64 a = R[j], b = R[j1];
            R[j]  = f2fma(g0, a, f2mul(g1, b));
            I[j]  = f2fma(g2, a, f2mul(g3, b));
            R[j1] = f2fma(g6, a, f2mul(g0, b));
            I[j1] = f2fma(g3, a, f2mul(g4, b));
        }
    }
}
// Controlled-1q (fusion of 1q(tgt) then CRX(ctrl,tgt)): ctrl bit KC, tgt bit KT.
// ctrl=0 branch applies gu (= U), ctrl=1 branch applies gv (= RX*U).
template<int KC,int KT>
__device__ __forceinline__ void c1q(u64 R[16], u64 I[16], const u64* gu, const u64* gv) {
    {
        const u64 g0 = gu[0], g1 = gu[1], g2 = gu[2], g3 = gu[3], g4 = gu[4], g5 = gu[5], g6 = gu[6];
#pragma unroll
        for (int j = 0; j < 16; j++)
            if (!((j >> KT) & 1) && !((j >> KC) & 1)) { const int j1 = j | (1 << KT); V1Q_BODY(j, j1); }
    }
    {
        const u64 g0 = gv[0], g1 = gv[1], g2 = gv[2], g3 = gv[3], g4 = gv[4], g5 = gv[5], g6 = gv[6];
#pragma unroll
        for (int j = 0; j < 16; j++)
            if (!((j >> KT) & 1) && ((j >> KC) & 1)) { const int j1 = j | (1 << KT); V1Q_BODY(j, j1); }
    }
}
// CRX: q[0]={c,c} q[1]={s,s} q[2]={-s,-s}
template<int KC,int KT>
__device__ __forceinline__ void vcrx(u64 R[16], u64 I[16], const u64* q) {
    const u64 q0 = q[0], q1 = q[1], q2 = q[2];
#pragma unroll
    for (int j = 0; j < 16; j++) {
        if (((j >> KC) & 1) && !((j >> KT) & 1)) {
            const int j1 = j | (1 << KT);
            const u64 a = R[j], ai = I[j], b = R[j1], bi = I[j1];
            R[j]  = f2fma(q0, a,  f2mul(q1, bi));
            I[j]  = f2fma(q0, ai, f2mul(q2, b));
            R[j1] = f2fma(q0, b,  f2mul(q1, ai));
            I[j1] = f2fma(q0, bi, f2mul(q2, a));
        }
    }
}

// Packed reduction: reduce u64 (2 batches) across warp, lane0 atomics both halves.
__device__ __forceinline__ void red_add2(u64 v, float* d0, float* d1) {
#pragma unroll
    for (int o = 16; o > 0; o >>= 1)
        v = f2add(v, __shfl_xor_sync(0xffffffffu, v, o));
    if ((threadIdx.x & 31) == 0) {
        float a, b; upk(v, a, b);
        atomicAdd(d0, a);
        atomicAdd(d1, b);
    }
}

// <X>,<Y> across local bit K (both batches at once)
template<int K>
__device__ __forceinline__ void vcross(const u64 R[16], const u64 I[16],
                                       float* feats0, float* feats1, int q) {
    u64 cr2 = 0ull, cip = 0ull, cin = 0ull;
#pragma unroll
    for (int j = 0; j < 16; j++) {
        if (!((j >> K) & 1)) {
            const int j1 = j | (1 << K);
            cr2 = f2fma(R[j], R[j1], f2fma(I[j], I[j1], cr2));
            cip = f2fma(R[j], I[j1], cip);
            cin = f2fma(I[j], R[j1], cin);
        }
    }
    const u64 crd = f2add(cr2, cr2);                 // 2*cr
    const u64 cid0 = f2sub(cip, cin);
    const u64 cid = f2add(cid0, cid0);               // 2*ci
    red_add2(crd, &feats0[q], &feats1[q]);
    red_add2(cid, &feats0[NQ + q], &feats1[NQ + q]);
}

// Compute fused-1q matrix U for (layer, wire) from angles.
__device__ __forceinline__ void fused_u(const float* angles, int layer, int wire, Cx& u00, Cx& u01) {
    const int base = layer * 48;
    const float tx = angles[base + wire];
    const float ty = angles[base + 12 + wire];
    const float tz = angles[base + 24 + wire];
    const float cxv = cosf(0.5f*tx), sxv = sinf(0.5f*tx);
    const float cyv = cosf(0.5f*ty), syv = sinf(0.5f*ty);
    const float czv = cosf(0.5f*tz), szv = sinf(0.5f*tz);
    Cx m00{cyv*cxv,  syv*sxv};
    Cx m01{-syv*cxv, -cyv*sxv};
    Cx ezm{czv, -szv};
    u00 = cmul(ezm, m00);
    u01 = cmul(ezm, m01);
}
// V = RX(theta) * U  (stays SU(2))
__device__ __forceinline__ void rx_compose(Cx u00, Cx u01, float c, float s, Cx& v00, Cx& v01) {
    v00 = Cx{c*u00.x + s*u01.y, c*u00.y + s*u01.x};
    v01 = Cx{c*u01.x - s*u00.y, c*u01.y - s*u00.x};
}

__global__ __launch_bounds__(THREADS, 2)
void qsim_kernel(const float* __restrict__ sv,
                 const float* __restrict__ angles,
                 const float* __restrict__ Wm,
                 const float* __restrict__ bv,
                 float* __restrict__ out)
{
    extern __shared__ u64 smem_state[];     // re2[4096] ++ im2[4096]  (64 KB)
    u64* re2 = smem_state;
    u64* im2 = smem_state + DIM;

    __shared__ u64 GS[24][8];     // SU(2)-compressed fused 1q coefs (7 used)
    __shared__ u64 FGS[12][8];    // fused V = RX(crx)*U coefs (ctrl=1 branches)
    __shared__ u64 CC[24][3];
    __shared__ float feats[2][NFEAT];

    const int tid  = threadIdx.x;
    const int bidx = blockIdx.x;

    if (tid < 24) {
        const int layer = tid / NQ;
        const int wire  = tid % NQ;
        Cx u00, u01;
        fused_u(angles, layer, wire, u00, u01);
        GS[tid][0] = splat(u00.x);  GS[tid][1] = splat(u01.x);
        GS[tid][2] = splat(u00.y);  GS[tid][3] = splat(u01.y);
        GS[tid][4] = splat(-u00.y); GS[tid][5] = splat(-u01.y);
        GS[tid][6] = splat(-u01.x); GS[tid][7] = 0ull;
        const float tc = angles[layer * 48 + 36 + wire];
        const float c = cosf(0.5f*tc), s = sinf(0.5f*tc);
        CC[tid][0] = pk(c, c); CC[tid][1] = pk(s, s); CC[tid][2] = pk(-s, -s);
    } else if (tid >= 32 && tid < 44) {
        // FGS[f]: fused V = RX(theta_crx) * U for:
        //   f=0..10 : (layer0, wire f+1) with L0 CRX slot f (angle angles[36+f])
        //   f=11    : (layer1, wire 0)  with L1 CRX(11,0) (angle angles[84])
        const int f = tid - 32;
        const int layer = (f == 11) ? 1 : 0;
        const int wire  = (f == 11) ? 0 : (f + 1);
        const float th  = (f == 11) ? angles[84] : angles[36 + f];
        Cx u00, u01, v00, v01;
        fused_u(angles, layer, wire, u00, u01);
        rx_compose(u00, u01, cosf(0.5f*th), sinf(0.5f*th), v00, v01);
        FGS[f][0] = splat(v00.x);  FGS[f][1] = splat(v01.x);
        FGS[f][2] = splat(v00.y);  FGS[f][3] = splat(v01.y);
        FGS[f][4] = splat(-v00.y); FGS[f][5] = splat(-v01.y);
        FGS[f][6] = splat(-v01.x); FGS[f][7] = 0ull;
    }
    if (tid < 2 * NFEAT) feats[0][tid] = 0.0f;   // feats contiguous [2][36]
    __syncthreads();

    u64 R[16], I[16];

    // ---- P1: S={8,9,10,11} (locals: b0=w3,b1=w2,b2=w1,b3=w0); gmem load ----
    {
        const float* in0 = sv + ((size_t)(2 * bidx))     * DIM;
        const float* in1 = sv + ((size_t)(2 * bidx) + 1) * DIM;
#pragma unroll
        for (int j = 0; j < 16; j++) {
            const int idx = (j << 8) | tid;
            R[j] = pk(in0[idx], in1[idx]);
            I[j] = 0ull;
        }
        v1q_real<3>(R, I, GS[0]);        // 1q w0 (bit11), state real
        c1q<3,2>(R, I, GS[1], FGS[0]);   // 1q w1 + CRX(0,1)  bits(11,10)
        c1q<2,1>(R, I, GS[2], FGS[1]);   // 1q w2 + CRX(1,2)  bits(10,9)
        c1q<1,0>(R, I, GS[3], FGS[2]);   // 1q w3 + CRX(2,3)  bits(9,8)
        vst<8,9,10,11>(R, I, re2, im2, swzc(tid));
    }
    __syncthreads();

    // ---- P2: S={5,6,7,8} (b0=w6,b1=w5,b2=w4,b3=w3) ----
    {
        const int pb = swzc(mkbase<0,1,2,3,4, 9,10,11>(tid));
        vld<5,6,7,8>(R, I, re2, im2, pb);
        c1q<3,2>(R, I, GS[4], FGS[3]);   // 1q w4 + CRX(3,4)  bits(8,7)
        c1q<2,1>(R, I, GS[5], FGS[4]);   // 1q w5 + CRX(4,5)  bits(7,6)
        c1q<1,0>(R, I, GS[6], FGS[5]);   // 1q w6 + CRX(5,6)  bits(6,5)
        vst<5,6,7,8>(R, I, re2, im2, pb);
    }
    __syncthreads();

    // ---- P3: S={2,3,4,5} (b0=w9,b1=w8,b2=w7,b3=w6) ----
    {
        const int pb = swzc(mkbase<0,1,7,8,9, 6,10,11>(tid));
        vld<2,3,4,5>(R, I, re2, im2, pb);
        c1q<3,2>(R, I, GS[7], FGS[6]);   // 1q w7 + CRX(6,7)  bits(5,4)
        c1q<2,1>(R, I, GS[8], FGS[7]);   // 1q w8 + CRX(7,8)  bits(4,3)
        c1q<1,0>(R, I, GS[9], FGS[8]);   // 1q w9 + CRX(8,9)  bits(3,2)
        vst<2,3,4,5>(R, I, re2, im2, pb);
    }
    __syncthreads();

    // ---- P4 (mega): S={0,1,2,11} (b0=w11,b1=w10,b2=w9,b3=w0); + X/Y q11,q10 ----
    {
        const int pb = swzc(mkbase<5,6,7,3,4, 8,9,10>(tid));
        vld<0,1,2,11>(R, I, re2, im2, pb);
        c1q<2,1>(R, I, GS[10], FGS[9]);  // L0 1q w10 + CRX(9,10)  bits(2,1)
        c1q<1,0>(R, I, GS[11], FGS[10]); // L0 1q w11 + CRX(10,11) bits(1,0)
        vcrx<0,3>(R, I, CC[11]);         // L0 CRX(11,0) (unfusable: ctrl had 1q before)
        v1q<0>(R, I, GS[23]);            // L1 1q w11
        v1q<1>(R, I, GS[22]);            // L1 1q w10
        v1q<2>(R, I, GS[21]);            // L1 1q w9
        c1q<0,3>(R, I, GS[12], FGS[11]); // L1 1q w0 + L1 CRX(11,0)  ctrl b0, tgt b11
        vcrx<1,0>(R, I, CC[13]);         // L1 CRX(10,11)
        vcrx<2,1>(R, I, CC[14]);         // L1 CRX(9,10)
        vst<0,1,2,11>(R, I, re2, im2, pb);
        // bits 0,1 untouched by P5-P7 -> expvals final now
        vcross<0>(R, I, feats[0], feats[1], 11);   // idx bit0 -> qubit 11
        vcross<1>(R, I, feats[0], feats[1], 10);   // idx bit1 -> qubit 10
    }
    __syncthreads();

    // ---- P5: S={2,3,4,5}; L1 1q 8,7,6; CRX 15,16,17; + X/Y q9,q8,q7 ----
    {
        const int pb = swzc(mkbase<0,1,7,8,9, 6,10,11>(tid));
        vld<2,3,4,5>(R, I, re2, im2, pb);
        v1q<1>(R, I, GS[20]);
        v1q<2>(R, I, GS[19]);
        v1q<3>(R, I, GS[18]);
        vcrx<1,0>(R, I, CC[15]);    // CRX(8,9): bits(3,2)
        vcrx<2,1>(R, I, CC[16]);    // CRX(7,8): bits(4,3)
        vcrx<3,2>(R, I, CC[17]);    // CRX(6,7): bits(5,4)
        vst<2,3,4,5>(R, I, re2, im2, pb);
        vcross<0>(R, I, feats[0], feats[1], 9);    // bit2 -> q9
        vcross<1>(R, I, feats[0], feats[1], 8);    // bit3 -> q8
        vcross<2>(R, I, feats[0], feats[1], 7);    // bit4 -> q7
    }
    __syncthreads();

    // ---- P6: S={5,6,7,8}; L1 1q 5,4,3; CRX 18,19,20; + X/Y q6,q5,q4 ----
    {
        const int pb = swzc(mkbase<0,1,2,3,4, 9,10,11>(tid));
        vld<5,6,7,8>(R, I, re2, im2, pb);
        v1q<1>(R, I, GS[17]);
        v1q<2>(R, I, GS[16]);
        v1q<3>(R, I, GS[15]);
        vcrx<1,0>(R, I, CC[18]);    // CRX(5,6): bits(6,5)
        vcrx<2,1>(R, I, CC[19]);    // CRX(4,5): bits(7,6)
        vcrx<3,2>(R, I, CC[20]);    // CRX(3,4): bits(8,7)
        vst<5,6,7,8>(R, I, re2, im2, pb);
        vcross<0>(R, I, feats[0], feats[1], 6);    // bit5 -> q6
        vcross<1>(R, I, feats[0], feats[1], 5);    // bit6 -> q5
        vcross<2>(R, I, feats[0], feats[1], 4);    // bit7 -> q4
    }
    __syncthreads();

    // ---- P7: S={8,9,10,11}; L1 1q 2,1; CRX 21,22,23; all Z + X/Y q3..q0. NO store. ----
    {
        const int pb = swzc(tid);
        vld<8,9,10,11>(R, I, re2, im2, pb);
        v1q<1>(R, I, GS[14]);       // wire2
        v1q<2>(R, I, GS[13]);       // wire1
        vcrx<1,0>(R, I, CC[21]);    // CRX(2,3)
        vcrx<2,1>(R, I, CC[22]);    // CRX(1,2)
        vcrx<3,2>(R, I, CC[23]);    // CRX(0,1)

        // |amp|^2 sums (packed per batch)
        u64 tot2 = 0ull, d0v = 0ull, d1v = 0ull, d2v = 0ull, d3v = 0ull;
#pragma unroll
        for (int j = 0; j < 16; j++) {
            const u64 p2 = f2fma(R[j], R[j], f2mul(I[j], I[j]));
            tot2 = f2add(tot2, p2);
            if (j & 1) d0v = f2add(d0v, p2);
            if (j & 2) d1v = f2add(d1v, p2);
            if (j & 4) d2v = f2add(d2v, p2);
            if (j & 8) d3v = f2add(d3v, p2);
        }
        // Z for tile bits 8..11 -> qubits 3..0
        red_add2(f2sub(tot2, f2add(d0v, d0v)), &feats[0][24+3], &feats[1][24+3]);
        red_add2(f2sub(tot2, f2add(d1v, d1v)), &feats[0][24+2], &feats[1][24+2]);
        red_add2(f2sub(tot2, f2add(d2v, d2v)), &feats[0][24+1], &feats[1][24+1]);
        red_add2(f2sub(tot2, f2add(d3v, d3v)), &feats[0][24+0], &feats[1][24+0]);

        // Z for free bits via 5-stage Walsh-Hadamard butterfly over the warp.
        {
            u64 x = tot2;
#pragma unroll
            for (int m = 1; m <= 16; m <<= 1) {
                const u64 y = __shfl_xor_sync(0xffffffffu, x, m);
                x = (tid & m) ? f2sub(y, x) : f2add(x, y);
            }
            const int lane = tid & 31;
            float a, b;
            if (lane == 1)  { upk(x, a, b); atomicAdd(&feats[0][24+11], a); atomicAdd(&feats[1][24+11], b); }
            if (lane == 2)  { upk(x, a, b); atomicAdd(&feats[0][24+10], a); atomicAdd(&feats[1][24+10], b); }
            if (lane == 4)  { upk(x, a, b); atomicAdd(&feats[0][24+9],  a); atomicAdd(&feats[1][24+9],  b); }
            if (lane == 8)  { upk(x, a, b); atomicAdd(&feats[0][24+8],  a); atomicAdd(&feats[1][24+8],  b); }
            if (lane == 16) { upk(x, a, b); atomicAdd(&feats[0][24+7],  a); atomicAdd(&feats[1][24+7],  b); }
            if (lane == 0) {
                upk(x, a, b);  // warp total, both batches
#pragma unroll
                for (int fb = 5; fb < 8; fb++) {
                    const float s = ((tid >> fb) & 1) ? -1.f : 1.f;
                    atomicAdd(&feats[0][24 + (11 - fb)], s * a);
                    atomicAdd(&feats[1][24 + (11 - fb)], s * b);
                }
            }
        }

        // X/Y for tile bits 8..11 -> qubits 3..0
        vcross<0>(R, I, feats[0], feats[1], 3);
        vcross<1>(R, I, feats[0], feats[1], 2);
        vcross<2>(R, I, feats[0], feats[1], 1);
        vcross<3>(R, I, feats[0], feats[1], 0);
    }
    __syncthreads();

    // ---- Linear head: 2 batches x 10 classes ----
    if (tid < 2 * NCLASSES) {
        const int batch = tid / NCLASSES;
        const int c     = tid % NCLASSES;
        float acc = bv[c];
#pragma unroll
        for (int j = 0; j < NFEAT; ++j)
            acc += Wm[c * NFEAT + j] * feats[batch][j];
        out[((size_t)(2 * bidx) + batch) * NCLASSES + c] = acc;
    }
}

extern "C" void kernel_launch(void* const* d_in, const int* in_sizes, int n_in,
                              void* d_out, int out_size)
{
    const float* sv     = (const float*)d_in[0];  // [2048, 4096]
    const float* angles = (const float*)d_in[1];  // [96]
    const float* Wm     = (const float*)d_in[2];  // [10, 36]
    const float* bv     = (const float*)d_in[3];  // [10]
    float* out          = (float*)d_out;          // [2048, 10]
    (void)in_sizes; (void)n_in; (void)out_size;

    const int smem_bytes = 2 * DIM * (int)sizeof(u64);  // 64 KB dynamic
    cudaFuncSetAttribute(qsim_kernel, cudaFuncAttributeMaxDynamicSharedMemorySize, smem_bytes);
    qsim_kernel<<<1024, THREADS, smem_bytes>>>(sv, angles, Wm, bv, out);
}

// round 12
// speedup vs baseline: 1.5752x; 1.1324x over previous
#include <cuda_runtime.h>

#define NQ       12
#define DIM      4096
#define THREADS  256
#define NCLASSES 10
#define NFEAT    36

typedef unsigned long long u64;

struct Cx { float x, y; };
__device__ __forceinline__ Cx cmul(Cx a, Cx b) {
    return Cx{a.x * b.x - a.y * b.y, a.x * b.y + a.y * b.x};
}

// ---- f32x2 helpers ----
__device__ __forceinline__ u64 pk(float lo, float hi) {
    u64 r; asm("mov.b64 %0, {%1,%2};" : "=l"(r) : "f"(lo), "f"(hi)); return r;
}
__device__ __forceinline__ void upk(u64 v, float& lo, float& hi) {
    asm("mov.b64 {%0,%1}, %2;" : "=f"(lo), "=f"(hi) : "l"(v));
}
__device__ __forceinline__ u64 f2fma(u64 a, u64 b, u64 c) {
    u64 r; asm("fma.rn.f32x2 %0, %1, %2, %3;" : "=l"(r) : "l"(a), "l"(b), "l"(c)); return r;
}
__device__ __forceinline__ u64 f2mul(u64 a, u64 b) {
    u64 r; asm("mul.rn.f32x2 %0, %1, %2;" : "=l"(r) : "l"(a), "l"(b)); return r;
}
__device__ __forceinline__ u64 f2add(u64 a, u64 b) {
    u64 r; asm("add.rn.f32x2 %0, %1, %2;" : "=l"(r) : "l"(a), "l"(b)); return r;
}
__device__ __forceinline__ u64 f2sub(u64 a, u64 b) {
    u64 r; asm("sub.rn.f32x2 %0, %1, %2;" : "=l"(r) : "l"(a), "l"(b)); return r;
}
__device__ __forceinline__ u64 splat(float x) { return pk(x, x); }

// ---- addressing ----
__device__ __forceinline__ int swzc(int i) { return i ^ ((i >> 5) & 31); }

template<int S0,int S1,int S2,int S3>
__device__ __forceinline__ int offj(int j) {
    return ((j & 1) << S0) | (((j >> 1) & 1) << S1) | (((j >> 2) & 1) << S2) | (((j >> 3) & 1) << S3);
}
template<int L0,int L1,int L2,int L3,int L4,int W0,int W1,int W2>
__device__ __forceinline__ int mkbase(int t) {
    return ((t & 1) << L0) | (((t >> 1) & 1) << L1) | (((t >> 2) & 1) << L2) |
           (((t >> 3) & 1) << L3) | (((t >> 4) & 1) << L4) |
           (((t >> 5) & 1) << W0) | (((t >> 6) & 1) << W1) | (((t >> 7) & 1) << W2);
}

// SMEM element: one amplitude = {R u64, I u64} (16 bytes) -> LDS.128/STS.128.
template<int S0,int S1,int S2,int S3>
__device__ __forceinline__ void vld(u64 R[16], u64 I[16], const longlong2* cxp, int pb) {
#pragma unroll
    for (int j = 0; j < 16; j++) {
        const int ad = pb ^ swzc(offj<S0,S1,S2,S3>(j));
        const longlong2 v = cxp[ad];
        R[j] = (u64)v.x; I[j] = (u64)v.y;
    }
}
template<int S0,int S1,int S2,int S3>
__device__ __forceinline__ void vst(const u64 R[16], const u64 I[16], longlong2* cxp, int pb) {
#pragma unroll
    for (int j = 0; j < 16; j++) {
        const int ad = pb ^ swzc(offj<S0,S1,S2,S3>(j));
        cxp[ad] = make_longlong2((long long)R[j], (long long)I[j]);
    }
}

// ---- gates ----
// SU(2): U = [[u00,u01],[-u01*,u00*]]
// GS: [0]=u00x [1]=u01x [2]=u00y [3]=u01y [4]=-u00y [5]=-u01y [6]=-u01x
#define V1Q_BODY(jlo, jhi) do {                                                  \
    const u64 a = R[jlo], ai = I[jlo], b = R[jhi], bi = I[jhi];                  \
    R[jlo] = f2fma(g0, a, f2fma(g4, ai, f2fma(g1, b, f2mul(g5, bi))));           \
    I[jlo] = f2fma(g2, a, f2fma(g0, ai, f2fma(g3, b, f2mul(g1, bi))));           \
    R[jhi] = f2fma(g6, a, f2fma(g5, ai, f2fma(g0, b, f2mul(g2, bi))));           \
    I[jhi] = f2fma(g3, a, f2fma(g6, ai, f2fma(g4, b, f2mul(g0, bi))));           \
} while (0)

template<int K>
__device__ __forceinline__ void v1q(u64 R[16], u64 I[16], const u64* g) {
    const u64 g0 = g[0], g1 = g[1], g2 = g[2], g3 = g[3], g4 = g[4], g5 = g[5], g6 = g[6];
#pragma unroll
    for (int j = 0; j < 16; j++) {
        if (!((j >> K) & 1)) { const int j1 = j | (1 << K); V1Q_BODY(j, j1); }
    }
}
template<int K>  // first gate on purely real state (I == 0)
__device__ __forceinline__ void v1q_real(u64 R[16], u64 I[16], const u64* g) {
    const u64 g0 = g[0], g1 = g[1], g2 = g[2], g3 = g[3], g4 = g[4], g6 = g[6];
#pragma unroll
    for (int j = 0; j < 16; j++) {
        if (!((j >> K) & 1)) {
            const int j1 = j | (1 << K);
            const u64 a = R[j], b = R[j1];
            R[j]  = f2fma(g0, a, f2mul(g1, b));
            I[j]  = f2fma(g2, a, f2mul(g3, b));
            R[j1] = f2fma(g6, a, f2mul(g0, b));
            I[j1] = f2fma(g3, a, f2mul(g4, b));
        }
    }
}
// Controlled-1q (fusion of 1q(tgt) then CRX(ctrl,tgt)): ctrl bit KC, tgt bit KT.
template<int KC,int KT>
__device__ __forceinline__ void c1q(u64 R[16], u64 I[16], const u64* gu, const u64* gv) {
    {
        const u64 g0 = gu[0], g1 = gu[1], g2 = gu[2], g3 = gu[3], g4 = gu[4], g5 = gu[5], g6 = gu[6];
#pragma unroll
        for (int j = 0; j < 16; j++)
            if (!((j >> KT) & 1) && !((j >> KC) & 1)) { const int j1 = j | (1 << KT); V1Q_BODY(j, j1); }
    }
    {
        const u64 g0 = gv[0], g1 = gv[1], g2 = gv[2], g3 = gv[3], g4 = gv[4], g5 = gv[5], g6 = gv[6];
#pragma unroll
        for (int j = 0; j < 16; j++)
            if (!((j >> KT) & 1) && ((j >> KC) & 1)) { const int j1 = j | (1 << KT); V1Q_BODY(j, j1); }
    }
}
// CRX: q[0]={c,c} q[1]={s,s} q[2]={-s,-s}
template<int KC,int KT>
__device__ __forceinline__ void vcrx(u64 R[16], u64 I[16], const u64* q) {
    const u64 q0 = q[0], q1 = q[1], q2 = q[2];
#pragma unroll
    for (int j = 0; j < 16; j++) {
        if (((j >> KC) & 1) && !((j >> KT) & 1)) {
            const int j1 = j | (1 << KT);
            const u64 a = R[j], ai = I[j], b = R[j1], bi = I[j1];
            R[j]  = f2fma(q0, a,  f2mul(q1, bi));
            I[j]  = f2fma(q0, ai, f2mul(q2, b));
            R[j1] = f2fma(q0, b,  f2mul(q1, ai));
            I[j1] = f2fma(q0, bi, f2mul(q2, a));
        }
    }
}

// Warp-reduce u64 (f32x2) and store to this warp's partial slot. No atomics.
__device__ __forceinline__ void red2w(u64 v, u64* dst) {
#pragma unroll
    for (int o = 16; o > 0; o >>= 1)
        v = f2add(v, __shfl_xor_sync(0xffffffffu, v, o));
    if ((threadIdx.x & 31) == 0) *dst = v;
}

// <X>,<Y> across local bit K. fwq = &FW[warp][0]; q = qubit index.
template<int K>
__device__ __forceinline__ void vcross(const u64 R[16], const u64 I[16], u64* fwq, int q) {
    u64 cr2 = 0ull, cip = 0ull, cin = 0ull;
#pragma unroll
    for (int j = 0; j < 16; j++) {
        if (!((j >> K) & 1)) {
            const int j1 = j | (1 << K);
            cr2 = f2fma(R[j], R[j1], f2fma(I[j], I[j1], cr2));
            cip = f2fma(R[j], I[j1], cip);
            cin = f2fma(I[j], R[j1], cin);
        }
    }
    const u64 crd = f2add(cr2, cr2);                 // 2*cr
    const u64 cid0 = f2sub(cip, cin);
    const u64 cid = f2add(cid0, cid0);               // 2*ci
    red2w(crd, fwq + q);
    red2w(cid, fwq + NQ + q);
}

// Fused-1q matrix U for (layer, wire).
__device__ __forceinline__ void fused_u(const float* angles, int layer, int wire, Cx& u00, Cx& u01) {
    const int base = layer * 48;
    const float tx = angles[base + wire];
    const float ty = angles[base + 12 + wire];
    const float tz = angles[base + 24 + wire];
    const float cxv = cosf(0.5f*tx), sxv = sinf(0.5f*tx);
    const float cyv = cosf(0.5f*ty), syv = sinf(0.5f*ty);
    const float czv = cosf(0.5f*tz), szv = sinf(0.5f*tz);
    Cx m00{cyv*cxv,  syv*sxv};
    Cx m01{-syv*cxv, -cyv*sxv};
    Cx ezm{czv, -szv};
    u00 = cmul(ezm, m00);
    u01 = cmul(ezm, m01);
}
// V = RX(theta) * U
__device__ __forceinline__ void rx_compose(Cx u00, Cx u01, float c, float s, Cx& v00, Cx& v01) {
    v00 = Cx{c*u00.x + s*u01.y, c*u00.y + s*u01.x};
    v01 = Cx{c*u01.x - s*u00.y, c*u01.y - s*u00.x};
}

__global__ __launch_bounds__(THREADS, 2)
void qsim_kernel(const float* __restrict__ sv,
                 const float* __restrict__ angles,
                 const float* __restrict__ Wm,
                 const float* __restrict__ bv,
                 float* __restrict__ out)
{
    extern __shared__ longlong2 cxp[];      // cxp[DIM] = {R,I} packed pairs, 64 KB

    __shared__ u64 GS[24][8];     // SU(2)-compressed fused 1q coefs
    __shared__ u64 FGS[12][8];    // fused V = RX(crx)*U coefs (ctrl=1 branches)
    __shared__ u64 CC[24][3];
    __shared__ u64 FW[8][NFEAT];  // per-warp feature partials (packed 2 batches)
    __shared__ u64 FZ[NFEAT];     // reduced features

    const int tid  = threadIdx.x;
    const int bidx = blockIdx.x;
    const int warp = tid >> 5;
    u64* fwq = &FW[warp][0];

    if (tid < 24) {
        const int layer = tid / NQ;
        const int wire  = tid % NQ;
        Cx u00, u01;
        fused_u(angles, layer, wire, u00, u01);
        GS[tid][0] = splat(u00.x);  GS[tid][1] = splat(u01.x);
        GS[tid][2] = splat(u00.y);  GS[tid][3] = splat(u01.y);
        GS[tid][4] = splat(-u00.y); GS[tid][5] = splat(-u01.y);
        GS[tid][6] = splat(-u01.x); GS[tid][7] = 0ull;
        const float tc = angles[layer * 48 + 36 + wire];
        const float c = cosf(0.5f*tc), s = sinf(0.5f*tc);
        CC[tid][0] = pk(c, c); CC[tid][1] = pk(s, s); CC[tid][2] = pk(-s, -s);
    } else if (tid >= 32 && tid < 44) {
        // FGS[f]: V = RX(theta_crx)*U; f=0..10: (L0, wire f+1, angle angles[36+f]);
        //         f=11: (L1, wire 0, angle angles[84])
        const int f = tid - 32;
        const int layer = (f == 11) ? 1 : 0;
        const int wire  = (f == 11) ? 0 : (f + 1);
        const float th  = (f == 11) ? angles[84] : angles[36 + f];
        Cx u00, u01, v00, v01;
        fused_u(angles, layer, wire, u00, u01);
        rx_compose(u00, u01, cosf(0.5f*th), sinf(0.5f*th), v00, v01);
        FGS[f][0] = splat(v00.x);  FGS[f][1] = splat(v01.x);
        FGS[f][2] = splat(v00.y);  FGS[f][3] = splat(v01.y);
        FGS[f][4] = splat(-v00.y); FGS[f][5] = splat(-v01.y);
        FGS[f][6] = splat(-v01.x); FGS[f][7] = 0ull;
    }
    __syncthreads();

    u64 R[16], I[16];

    // ---- P1: S={8,9,10,11} (b0=w3,b1=w2,b2=w1,b3=w0); gmem load ----
    {
        const float* in0 = sv + ((size_t)(2 * bidx))     * DIM;
        const float* in1 = sv + ((size_t)(2 * bidx) + 1) * DIM;
#pragma unroll
        for (int j = 0; j < 16; j++) {
            const int idx = (j << 8) | tid;
            R[j] = pk(in0[idx], in1[idx]);
            I[j] = 0ull;
        }
        v1q_real<3>(R, I, GS[0]);        // 1q w0 (bit11), state real
        c1q<3,2>(R, I, GS[1], FGS[0]);   // 1q w1 + CRX(0,1)
        c1q<2,1>(R, I, GS[2], FGS[1]);   // 1q w2 + CRX(1,2)
        c1q<1,0>(R, I, GS[3], FGS[2]);   // 1q w3 + CRX(2,3)
        vst<8,9,10,11>(R, I, cxp, swzc(tid));
    }
    __syncthreads();

    // ---- P2: S={5,6,7,8} ----
    {
        const int pb = swzc(mkbase<0,1,2,3,4, 9,10,11>(tid));
        vld<5,6,7,8>(R, I, cxp, pb);
        c1q<3,2>(R, I, GS[4], FGS[3]);   // 1q w4 + CRX(3,4)
        c1q<2,1>(R, I, GS[5], FGS[4]);   // 1q w5 + CRX(4,5)
        c1q<1,0>(R, I, GS[6], FGS[5]);   // 1q w6 + CRX(5,6)
        vst<5,6,7,8>(R, I, cxp, pb);
    }
    __syncthreads();

    // ---- P3: S={2,3,4,5} ----
    {
        const int pb = swzc(mkbase<0,1,7,8,9, 6,10,11>(tid));
        vld<2,3,4,5>(R, I, cxp, pb);
        c1q<3,2>(R, I, GS[7], FGS[6]);   // 1q w7 + CRX(6,7)
        c1q<2,1>(R, I, GS[8], FGS[7]);   // 1q w8 + CRX(7,8)
        c1q<1,0>(R, I, GS[9], FGS[8]);   // 1q w9 + CRX(8,9)
        vst<2,3,4,5>(R, I, cxp, pb);
    }
    __syncthreads();

    // ---- P4 (mega): S={0,1,2,11}; + X/Y q11,q10 ----
    {
        const int pb = swzc(mkbase<5,6,7,3,4, 8,9,10>(tid));
        vld<0,1,2,11>(R, I, cxp, pb);
        c1q<2,1>(R, I, GS[10], FGS[9]);  // L0 1q w10 + CRX(9,10)
        c1q<1,0>(R, I, GS[11], FGS[10]); // L0 1q w11 + CRX(10,11)
        vcrx<0,3>(R, I, CC[11]);         // L0 CRX(11,0)
        v1q<0>(R, I, GS[23]);            // L1 1q w11
        v1q<1>(R, I, GS[22]);            // L1 1q w10
        v1q<2>(R, I, GS[21]);            // L1 1q w9
        c1q<0,3>(R, I, GS[12], FGS[11]); // L1 1q w0 + L1 CRX(11,0)
        vcrx<1,0>(R, I, CC[13]);         // L1 CRX(10,11)
        vcrx<2,1>(R, I, CC[14]);         // L1 CRX(9,10)
        vst<0,1,2,11>(R, I, cxp, pb);
        vcross<0>(R, I, fwq, 11);        // idx bit0 -> qubit 11 (final)
        vcross<1>(R, I, fwq, 10);        // idx bit1 -> qubit 10 (final)
    }
    __syncthreads();

    // ---- P5: S={2,3,4,5}; L1 1q 8,7,6; CRX 15,16,17; + X/Y q9,q8,q7 ----
    {
        const int pb = swzc(mkbase<0,1,7,8,9, 6,10,11>(tid));
        vld<2,3,4,5>(R, I, cxp, pb);
        v1q<1>(R, I, GS[20]);
        v1q<2>(R, I, GS[19]);
        v1q<3>(R, I, GS[18]);
        vcrx<1,0>(R, I, CC[15]);    // CRX(8,9)
        vcrx<2,1>(R, I, CC[16]);    // CRX(7,8)
        vcrx<3,2>(R, I, CC[17]);    // CRX(6,7)
        vst<2,3,4,5>(R, I, cxp, pb);
        vcross<0>(R, I, fwq, 9);
        vcross<1>(R, I, fwq, 8);
        vcross<2>(R, I, fwq, 7);
    }
    __syncthreads();

    // ---- P6: S={5,6,7,8}; L1 1q 5,4,3; CRX 18,19,20; + X/Y q6,q5,q4 ----
    {
        const int pb = swzc(mkbase<0,1,2,3,4, 9,10,11>(tid));
        vld<5,6,7,8>(R, I, cxp, pb);
        v1q<1>(R, I, GS[17]);
        v1q<2>(R, I, GS[16]);
        v1q<3>(R, I, GS[15]);
        vcrx<1,0>(R, I, CC[18]);    // CRX(5,6)
        vcrx<2,1>(R, I, CC[19]);    // CRX(4,5)
        vcrx<3,2>(R, I, CC[20]);    // CRX(3,4)
        vst<5,6,7,8>(R, I, cxp, pb);
        vcross<0>(R, I, fwq, 6);
        vcross<1>(R, I, fwq, 5);
        vcross<2>(R, I, fwq, 4);
    }
    __syncthreads();

    // ---- P7: S={8,9,10,11}; L1 1q 2,1; CRX 21,22,23; all Z + X/Y q3..q0. NO store. ----
    {
        const int pb = swzc(tid);
        vld<8,9,10,11>(R, I, cxp, pb);
        v1q<1>(R, I, GS[14]);       // wire2
        v1q<2>(R, I, GS[13]);       // wire1
        vcrx<1,0>(R, I, CC[21]);    // CRX(2,3)
        vcrx<2,1>(R, I, CC[22]);    // CRX(1,2)
        vcrx<3,2>(R, I, CC[23]);    // CRX(0,1)

        // |amp|^2 sums (packed per batch)
        u64 tot2 = 0ull, d0v = 0ull, d1v = 0ull, d2v = 0ull, d3v = 0ull;
#pragma unroll
        for (int j = 0; j < 16; j++) {
            const u64 p2 = f2fma(R[j], R[j], f2mul(I[j], I[j]));
            tot2 = f2add(tot2, p2);
            if (j & 1) d0v = f2add(d0v, p2);
            if (j & 2) d1v = f2add(d1v, p2);
            if (j & 4) d2v = f2add(d2v, p2);
            if (j & 8) d3v = f2add(d3v, p2);
        }
        // Z for tile bits 8..11 -> qubits 3..0
        red2w(f2sub(tot2, f2add(d0v, d0v)), fwq + 24 + 3);
        red2w(f2sub(tot2, f2add(d1v, d1v)), fwq + 24 + 2);
        red2w(f2sub(tot2, f2add(d2v, d2v)), fwq + 24 + 1);
        red2w(f2sub(tot2, f2add(d3v, d3v)), fwq + 24 + 0);

        // Z for free bits: 5-stage Walsh-Hadamard butterfly over the warp.
        {
            u64 x = tot2;
#pragma unroll
            for (int m = 1; m <= 16; m <<= 1) {
                const u64 y = __shfl_xor_sync(0xffffffffu, x, m);
                x = (tid & m) ? f2sub(y, x) : f2add(x, y);
            }
            const int lane = tid & 31;
            if (lane == 1)  fwq[24 + 11] = x;   // fb0 -> q11
            if (lane == 2)  fwq[24 + 10] = x;   // fb1 -> q10
            if (lane == 4)  fwq[24 + 9]  = x;   // fb2 -> q9
            if (lane == 8)  fwq[24 + 8]  = x;   // fb3 -> q8
            if (lane == 16) fwq[24 + 7]  = x;   // fb4 -> q7
            if (lane == 0) {
#pragma unroll
                for (int fb = 5; fb < 8; fb++) {   // warp-uniform sign bits -> q6,q5,q4
                    const u64 v = ((tid >> fb) & 1) ? f2sub(0ull, x) : x;
                    fwq[24 + (11 - fb)] = v;
                }
            }
        }

        // X/Y for tile bits 8..11 -> qubits 3..0
        vcross<0>(R, I, fwq, 3);
        vcross<1>(R, I, fwq, 2);
        vcross<2>(R, I, fwq, 1);
        vcross<3>(R, I, fwq, 0);
    }
    __syncthreads();

    // ---- Reduce per-warp partials, then linear head ----
    if (tid < NFEAT) {
        u64 acc = FW[0][tid];
#pragma unroll
        for (int w = 1; w < 8; w++) acc = f2add(acc, FW[w][tid]);
        FZ[tid] = acc;
    }
    __syncthreads();

    if (tid < 2 * NCLASSES) {
        const int batch = tid / NCLASSES;
        const int c     = tid % NCLASSES;
        const float* fz = (const float*)FZ;     // {b0,b1} interleaved per feature
        float acc = bv[c];
#pragma unroll
        for (int j = 0; j < NFEAT; ++j)
            acc += Wm[c * NFEAT + j] * fz[2 * j + batch];
        out[((size_t)(2 * bidx) + batch) * NCLASSES + c] = acc;
    }
}

extern "C" void kernel_launch(void* const* d_in, const int* in_sizes, int n_in,
                              void* d_out, int out_size)
{
    const float* sv     = (const float*)d_in[0];  // [2048, 4096]
    const float* angles = (const float*)d_in[1];  // [96]
    const float* Wm     = (const float*)d_in[2];  // [10, 36]
    const float* bv     = (const float*)d_in[3];  // [10]
    float* out          = (float*)d_out;          // [2048, 10]
    (void)in_sizes; (void)n_in; (void)out_size;

    const int smem_bytes = DIM * (int)sizeof(longlong2);  // 64 KB dynamic
    cudaFuncSetAttribute(qsim_kernel, cudaFuncAttributeMaxDynamicSharedMemorySize, smem_bytes);
    qsim_kernel<<<1024, THREADS, smem_bytes>>>(sv, angles, Wm, bv, out);
}

// round 13
// speedup vs baseline: 1.5869x; 1.0075x over previous
#include <cuda_runtime.h>

#define NQ       12
#define DIM      4096
#define THREADS  256
#define NCLASSES 10
#define NFEAT    36

typedef unsigned long long u64;

struct Cx { float x, y; };
__device__ __forceinline__ Cx cmul(Cx a, Cx b) {
    return Cx{a.x * b.x - a.y * b.y, a.x * b.y + a.y * b.x};
}

// ---- f32x2 helpers ----
__device__ __forceinline__ u64 pk(float lo, float hi) {
    u64 r; asm("mov.b64 %0, {%1,%2};" : "=l"(r) : "f"(lo), "f"(hi)); return r;
}
__device__ __forceinline__ void upk(u64 v, float& lo, float& hi) {
    asm("mov.b64 {%0,%1}, %2;" : "=f"(lo), "=f"(hi) : "l"(v));
}
__device__ __forceinline__ u64 f2fma(u64 a, u64 b, u64 c) {
    u64 r; asm("fma.rn.f32x2 %0, %1, %2, %3;" : "=l"(r) : "l"(a), "l"(b), "l"(c)); return r;
}
__device__ __forceinline__ u64 f2mul(u64 a, u64 b) {
    u64 r; asm("mul.rn.f32x2 %0, %1, %2;" : "=l"(r) : "l"(a), "l"(b)); return r;
}
__device__ __forceinline__ u64 f2add(u64 a, u64 b) {
    u64 r; asm("add.rn.f32x2 %0, %1, %2;" : "=l"(r) : "l"(a), "l"(b)); return r;
}
__device__ __forceinline__ u64 f2sub(u64 a, u64 b) {
    u64 r; asm("sub.rn.f32x2 %0, %1, %2;" : "=l"(r) : "l"(a), "l"(b)); return r;
}
__device__ __forceinline__ u64 splat(float x) { return pk(x, x); }

// ---- addressing ----
__device__ __forceinline__ int swzc(int i) { return i ^ ((i >> 5) & 31); }

template<int S0,int S1,int S2,int S3>
__device__ __forceinline__ int offj(int j) {
    return ((j & 1) << S0) | (((j >> 1) & 1) << S1) | (((j >> 2) & 1) << S2) | (((j >> 3) & 1) << S3);
}
template<int L0,int L1,int L2,int L3,int L4,int W0,int W1,int W2>
__device__ __forceinline__ int mkbase(int t) {
    return ((t & 1) << L0) | (((t >> 1) & 1) << L1) | (((t >> 2) & 1) << L2) |
           (((t >> 3) & 1) << L3) | (((t >> 4) & 1) << L4) |
           (((t >> 5) & 1) << W0) | (((t >> 6) & 1) << W1) | (((t >> 7) & 1) << W2);
}

// SMEM element: one amplitude = {R u64, I u64} (16 bytes) -> LDS.128/STS.128.
template<int S0,int S1,int S2,int S3>
__device__ __forceinline__ void vld(u64 R[16], u64 I[16], const longlong2* cxp, int pb) {
#pragma unroll
    for (int j = 0; j < 16; j++) {
        const int ad = pb ^ swzc(offj<S0,S1,S2,S3>(j));
        const longlong2 v = cxp[ad];
        R[j] = (u64)v.x; I[j] = (u64)v.y;
    }
}
template<int S0,int S1,int S2,int S3>
__device__ __forceinline__ void vst(const u64 R[16], const u64 I[16], longlong2* cxp, int pb) {
#pragma unroll
    for (int j = 0; j < 16; j++) {
        const int ad = pb ^ swzc(offj<S0,S1,S2,S3>(j));
        cxp[ad] = make_longlong2((long long)R[j], (long long)I[j]);
    }
}

// ---- gates ----
// SU(2): U = [[u00,u01],[-u01*,u00*]]
// GS: [0]=u00x [1]=u01x [2]=u00y [3]=u01y [4]=-u00y [5]=-u01y [6]=-u01x
#define V1Q_BODY(jlo, jhi) do {                                                  \
    const u64 a = R[jlo], ai = I[jlo], b = R[jhi], bi = I[jhi];                  \
    R[jlo] = f2fma(g0, a, f2fma(g4, ai, f2fma(g1, b, f2mul(g5, bi))));           \
    I[jlo] = f2fma(g2, a, f2fma(g0, ai, f2fma(g3, b, f2mul(g1, bi))));           \
    R[jhi] = f2fma(g6, a, f2fma(g5, ai, f2fma(g0, b, f2mul(g2, bi))));           \
    I[jhi] = f2fma(g3, a, f2fma(g6, ai, f2fma(g4, b, f2mul(g0, bi))));           \
} while (0)

template<int K>
__device__ __forceinline__ void v1q(u64 R[16], u64 I[16], const u64* g) {
    const u64 g0 = g[0], g1 = g[1], g2 = g[2], g3 = g[3], g4 = g[4], g5 = g[5], g6 = g[6];
#pragma unroll
    for (int j = 0; j < 16; j++) {
        if (!((j >> K) & 1)) { const int j1 = j | (1 << K); V1Q_BODY(j, j1); }
    }
}
template<int K>  // first gate on purely real state (I == 0)
__device__ __forceinline__ void v1q_real(u64 R[16], u64 I[16], const u64* g) {
    const u64 g0 = g[0], g1 = g[1], g2 = g[2], g3 = g[3], g4 = g[4], g6 = g[6];
#pragma unroll
    for (int j = 0; j < 16; j++) {
        if (!((j >> K) & 1)) {
            const int j1 = j | (1 << K);
            const u64 a = R[j], b = R[j1];
            R[j]  = f2fma(g0, a, f2mul(g1, b));
            I[j]  = f2fma(g2, a, f2mul(g3, b));
            R[j1] = f2fma(g6, a, f2mul(g0, b));
            I[j1] = f2fma(g3, a, f2mul(g4, b));
        }
    }
}
// Controlled-1q (fusion of 1q(tgt) then CRX(ctrl,tgt)): ctrl bit KC, tgt bit KT.
template<int KC,int KT>
__device__ __forceinline__ void c1q(u64 R[16], u64 I[16], const u64* gu, const u64* gv) {
    {
        const u64 g0 = gu[0], g1 = gu[1], g2 = gu[2], g3 = gu[3], g4 = gu[4], g5 = gu[5], g6 = gu[6];
#pragma unroll
        for (int j = 0; j < 16; j++)
            if (!((j >> KT) & 1) && !((j >> KC) & 1)) { const int j1 = j | (1 << KT); V1Q_BODY(j, j1); }
    }
    {
        const u64 g0 = gv[0], g1 = gv[1], g2 = gv[2], g3 = gv[3], g4 = gv[4], g5 = gv[5], g6 = gv[6];
#pragma unroll
        for (int j = 0; j < 16; j++)
            if (!((j >> KT) & 1) && ((j >> KC) & 1)) { const int j1 = j | (1 << KT); V1Q_BODY(j, j1); }
    }
}
// CRX: q[0]={c,c} q[1]={s,s} q[2]={-s,-s}
template<int KC,int KT>
__device__ __forceinline__ void vcrx(u64 R[16], u64 I[16], const u64* q) {
    const u64 q0 = q[0], q1 = q[1], q2 = q[2];
#pragma unroll
    for (int j = 0; j < 16; j++) {
        if (((j >> KC) & 1) && !((j >> KT) & 1)) {
            const int j1 = j | (1 << KT);
            const u64 a = R[j], ai = I[j], b = R[j1], bi = I[j1];
            R[j]  = f2fma(q0, a,  f2mul(q1, bi));
            I[j]  = f2fma(q0, ai, f2mul(q2, b));
            R[j1] = f2fma(q0, b,  f2mul(q1, ai));
            I[j1] = f2fma(q0, bi, f2mul(q2, a));
        }
    }
}

// ---- reductions ----
// 3-stage warp reduce (lanes 0-3 hold disjoint partials); store 4 partials per warp.
__device__ __forceinline__ void red2w4(u64 v, u64* fw4, int feat) {
    v = f2add(v, __shfl_xor_sync(0xffffffffu, v, 16));
    v = f2add(v, __shfl_xor_sync(0xffffffffu, v, 8));
    v = f2add(v, __shfl_xor_sync(0xffffffffu, v, 4));
    const int lane = threadIdx.x & 31;
    if (lane < 4) fw4[lane * NFEAT + feat] = v;
}

struct XY { u64 cr, cp, cn; };
// FMA-only accumulation phase of <X>,<Y> across local bit K.
template<int K>
__device__ __forceinline__ XY vcross_acc(const u64 R[16], const u64 I[16]) {
    u64 cr = 0ull, cp = 0ull, cn = 0ull;
#pragma unroll
    for (int j = 0; j < 16; j++) {
        if (!((j >> K) & 1)) {
            const int j1 = j | (1 << K);
            cr = f2fma(R[j], R[j1], f2fma(I[j], I[j1], cr));
            cp = f2fma(R[j], I[j1], cp);
            cn = f2fma(I[j], R[j1], cn);
        }
    }
    return XY{cr, cp, cn};
}
// Shuffle/store finish phase (deferred into next pass's load shadow).
__device__ __forceinline__ void vcross_fin(XY a, u64* fw4, int q) {
    red2w4(f2add(a.cr, a.cr), fw4, q);
    const u64 ci = f2sub(a.cp, a.cn);
    red2w4(f2add(ci, ci), fw4, NQ + q);
}

// Fused-1q matrix U for (layer, wire).
__device__ __forceinline__ void fused_u(const float* angles, int layer, int wire, Cx& u00, Cx& u01) {
    const int base = layer * 48;
    const float tx = angles[base + wire];
    const float ty = angles[base + 12 + wire];
    const float tz = angles[base + 24 + wire];
    const float cxv = cosf(0.5f*tx), sxv = sinf(0.5f*tx);
    const float cyv = cosf(0.5f*ty), syv = sinf(0.5f*ty);
    const float czv = cosf(0.5f*tz), szv = sinf(0.5f*tz);
    Cx m00{cyv*cxv,  syv*sxv};
    Cx m01{-syv*cxv, -cyv*sxv};
    Cx ezm{czv, -szv};
    u00 = cmul(ezm, m00);
    u01 = cmul(ezm, m01);
}
// V = RX(theta) * U
__device__ __forceinline__ void rx_compose(Cx u00, Cx u01, float c, float s, Cx& v00, Cx& v01) {
    v00 = Cx{c*u00.x + s*u01.y, c*u00.y + s*u01.x};
    v01 = Cx{c*u01.x - s*u00.y, c*u01.y - s*u00.x};
}

__global__ __launch_bounds__(THREADS, 2)
void qsim_kernel(const float* __restrict__ sv,
                 const float* __restrict__ angles,
                 const float* __restrict__ Wm,
                 const float* __restrict__ bv,
                 float* __restrict__ out)
{
    extern __shared__ longlong2 cxp[];      // cxp[DIM] = {R,I} packed pairs, 64 KB

    __shared__ u64 GS[24][8];     // SU(2)-compressed fused 1q coefs
    __shared__ u64 FGS[12][8];    // fused V = RX(crx)*U coefs (ctrl=1 branches)
    __shared__ u64 CC[24][3];
    __shared__ u64 FW[32][NFEAT]; // 4 partials per warp, packed 2 batches
    __shared__ u64 FZ[NFEAT];     // reduced features

    const int tid  = threadIdx.x;
    const int bidx = blockIdx.x;
    const int warp = tid >> 5;
    u64* fw4 = &FW[warp * 4][0];

    u64 R[16], I[16];

    // ---- Hoisted gmem load: issue LDGs first; latency hides under coef setup ----
    {
        const float* in0 = sv + ((size_t)(2 * bidx))     * DIM;
        const float* in1 = sv + ((size_t)(2 * bidx) + 1) * DIM;
#pragma unroll
        for (int j = 0; j < 16; j++) {
            const int idx = (j << 8) | tid;
            R[j] = pk(in0[idx], in1[idx]);
            I[j] = 0ull;
        }
    }

    // ---- Coefficient setup ----
    if (tid < 24) {
        const int layer = tid / NQ;
        const int wire  = tid % NQ;
        Cx u00, u01;
        fused_u(angles, layer, wire, u00, u01);
        GS[tid][0] = splat(u00.x);  GS[tid][1] = splat(u01.x);
        GS[tid][2] = splat(u00.y);  GS[tid][3] = splat(u01.y);
        GS[tid][4] = splat(-u00.y); GS[tid][5] = splat(-u01.y);
        GS[tid][6] = splat(-u01.x); GS[tid][7] = 0ull;
        const float tc = angles[layer * 48 + 36 + wire];
        const float c = cosf(0.5f*tc), s = sinf(0.5f*tc);
        CC[tid][0] = pk(c, c); CC[tid][1] = pk(s, s); CC[tid][2] = pk(-s, -s);
    } else if (tid >= 32 && tid < 44) {
        // FGS[f]: V = RX(theta_crx)*U; f=0..10: (L0, wire f+1, angle angles[36+f]);
        //         f=11: (L1, wire 0, angle angles[84])
        const int f = tid - 32;
        const int layer = (f == 11) ? 1 : 0;
        const int wire  = (f == 11) ? 0 : (f + 1);
        const float th  = (f == 11) ? angles[84] : angles[36 + f];
        Cx u00, u01, v00, v01;
        fused_u(angles, layer, wire, u00, u01);
        rx_compose(u00, u01, cosf(0.5f*th), sinf(0.5f*th), v00, v01);
        FGS[f][0] = splat(v00.x);  FGS[f][1] = splat(v01.x);
        FGS[f][2] = splat(v00.y);  FGS[f][3] = splat(v01.y);
        FGS[f][4] = splat(-v00.y); FGS[f][5] = splat(-v01.y);
        FGS[f][6] = splat(-v01.x); FGS[f][7] = 0ull;
    }
    // Zero feature partials (rows not written by WHT lanes must be 0).
#pragma unroll
    for (int i = tid; i < 32 * NFEAT; i += THREADS) ((u64*)FW)[i] = 0ull;
    __syncthreads();

    // ---- P1: S={8,9,10,11} (b0=w3,b1=w2,b2=w1,b3=w0) ----
    {
        v1q_real<3>(R, I, GS[0]);        // 1q w0 (bit11), state real
        c1q<3,2>(R, I, GS[1], FGS[0]);   // 1q w1 + CRX(0,1)
        c1q<2,1>(R, I, GS[2], FGS[1]);   // 1q w2 + CRX(1,2)
        c1q<1,0>(R, I, GS[3], FGS[2]);   // 1q w3 + CRX(2,3)
        vst<8,9,10,11>(R, I, cxp, swzc(tid));
    }
    __syncthreads();

    // ---- P2: S={5,6,7,8} ----
    {
        const int pb = swzc(mkbase<0,1,2,3,4, 9,10,11>(tid));
        vld<5,6,7,8>(R, I, cxp, pb);
        c1q<3,2>(R, I, GS[4], FGS[3]);   // 1q w4 + CRX(3,4)
        c1q<2,1>(R, I, GS[5], FGS[4]);   // 1q w5 + CRX(4,5)
        c1q<1,0>(R, I, GS[6], FGS[5]);   // 1q w6 + CRX(5,6)
        vst<5,6,7,8>(R, I, cxp, pb);
    }
    __syncthreads();

    // ---- P3: S={2,3,4,5} ----
    {
        const int pb = swzc(mkbase<0,1,7,8,9, 6,10,11>(tid));
        vld<2,3,4,5>(R, I, cxp, pb);
        c1q<3,2>(R, I, GS[7], FGS[6]);   // 1q w7 + CRX(6,7)
        c1q<2,1>(R, I, GS[8], FGS[7]);   // 1q w8 + CRX(7,8)
        c1q<1,0>(R, I, GS[9], FGS[8]);   // 1q w9 + CRX(8,9)
        vst<2,3,4,5>(R, I, cxp, pb);
    }
    __syncthreads();

    XY a11, a10;     // deferred from P4
    // ---- P4 (mega): S={0,1,2,11} ----
    {
        const int pb = swzc(mkbase<5,6,7,3,4, 8,9,10>(tid));
        vld<0,1,2,11>(R, I, cxp, pb);
        c1q<2,1>(R, I, GS[10], FGS[9]);  // L0 1q w10 + CRX(9,10)
        c1q<1,0>(R, I, GS[11], FGS[10]); // L0 1q w11 + CRX(10,11)
        vcrx<0,3>(R, I, CC[11]);         // L0 CRX(11,0)
        v1q<0>(R, I, GS[23]);            // L1 1q w11
        v1q<1>(R, I, GS[22]);            // L1 1q w10
        v1q<2>(R, I, GS[21]);            // L1 1q w9
        c1q<0,3>(R, I, GS[12], FGS[11]); // L1 1q w0 + L1 CRX(11,0)
        vcrx<1,0>(R, I, CC[13]);         // L1 CRX(10,11)
        vcrx<2,1>(R, I, CC[14]);         // L1 CRX(9,10)
        vst<0,1,2,11>(R, I, cxp, pb);
        a11 = vcross_acc<0>(R, I);       // idx bit0 -> qubit 11 (final)
        a10 = vcross_acc<1>(R, I);       // idx bit1 -> qubit 10 (final)
    }
    __syncthreads();

    XY a9, a8, a7;   // deferred from P5
    // ---- P5: S={2,3,4,5}; fin(P4) in load shadow ----
    {
        const int pb = swzc(mkbase<0,1,7,8,9, 6,10,11>(tid));
        vld<2,3,4,5>(R, I, cxp, pb);
        vcross_fin(a11, fw4, 11);
        vcross_fin(a10, fw4, 10);
        v1q<1>(R, I, GS[20]);
        v1q<2>(R, I, GS[19]);
        v1q<3>(R, I, GS[18]);
        vcrx<1,0>(R, I, CC[15]);    // CRX(8,9)
        vcrx<2,1>(R, I, CC[16]);    // CRX(7,8)
        vcrx<3,2>(R, I, CC[17]);    // CRX(6,7)
        vst<2,3,4,5>(R, I, cxp, pb);
        a9 = vcross_acc<0>(R, I);
        a8 = vcross_acc<1>(R, I);
        a7 = vcross_acc<2>(R, I);
    }
    __syncthreads();

    XY a6, a5, a4;   // deferred from P6
    // ---- P6: S={5,6,7,8}; fin(P5) in load shadow ----
    {
        const int pb = swzc(mkbase<0,1,2,3,4, 9,10,11>(tid));
        vld<5,6,7,8>(R, I, cxp, pb);
        vcross_fin(a9, fw4, 9);
        vcross_fin(a8, fw4, 8);
        vcross_fin(a7, fw4, 7);
        v1q<1>(R, I, GS[17]);
        v1q<2>(R, I, GS[16]);
        v1q<3>(R, I, GS[15]);
        vcrx<1,0>(R, I, CC[18]);    // CRX(5,6)
        vcrx<2,1>(R, I, CC[19]);    // CRX(4,5)
        vcrx<3,2>(R, I, CC[20]);    // CRX(3,4)
        vst<5,6,7,8>(R, I, cxp, pb);
        a6 = vcross_acc<0>(R, I);
        a5 = vcross_acc<1>(R, I);
        a4 = vcross_acc<2>(R, I);
    }
    __syncthreads();

    // ---- P7: S={8,9,10,11}; fin(P6) in load shadow; all Z + X/Y q3..q0. NO store. ----
    {
        const int pb = swzc(tid);
        vld<8,9,10,11>(R, I, cxp, pb);
        vcross_fin(a6, fw4, 6);
        vcross_fin(a5, fw4, 5);
        vcross_fin(a4, fw4, 4);
        v1q<1>(R, I, GS[14]);       // wire2
        v1q<2>(R, I, GS[13]);       // wire1
        vcrx<1,0>(R, I, CC[21]);    // CRX(2,3)
        vcrx<2,1>(R, I, CC[22]);    // CRX(1,2)
        vcrx<3,2>(R, I, CC[23]);    // CRX(0,1)

        // |amp|^2 sums (packed per batch)
        u64 tot2 = 0ull, d0v = 0ull, d1v = 0ull, d2v = 0ull, d3v = 0ull;
#pragma unroll
        for (int j = 0; j < 16; j++) {
            const u64 p2 = f2fma(R[j], R[j], f2mul(I[j], I[j]));
            tot2 = f2add(tot2, p2);
            if (j & 1) d0v = f2add(d0v, p2);
            if (j & 2) d1v = f2add(d1v, p2);
            if (j & 4) d2v = f2add(d2v, p2);
            if (j & 8) d3v = f2add(d3v, p2);
        }
        // Z for tile bits 8..11 -> qubits 3..0
        red2w4(f2sub(tot2, f2add(d0v, d0v)), fw4, 24 + 3);
        red2w4(f2sub(tot2, f2add(d1v, d1v)), fw4, 24 + 2);
        red2w4(f2sub(tot2, f2add(d2v, d2v)), fw4, 24 + 1);
        red2w4(f2sub(tot2, f2add(d3v, d3v)), fw4, 24 + 0);

        // Z for free bits: 5-stage Walsh-Hadamard butterfly over the warp.
        {
            u64 x = tot2;
#pragma unroll
            for (int m = 1; m <= 16; m <<= 1) {
                const u64 y = __shfl_xor_sync(0xffffffffu, x, m);
                x = (tid & m) ? f2sub(y, x) : f2add(x, y);
            }
            const int lane = tid & 31;
            if (lane == 1)  fw4[24 + 11] = x;   // fb0 -> q11  (row warp*4+0 unused by others? no: row 0 holds lane-0 partials of red2w4 writes for OTHER features; feature columns disjoint)
            if (lane == 2)  fw4[24 + 10] = x;   // fb1 -> q10
            if (lane == 4)  fw4[24 + 9]  = x;   // fb2 -> q9
            if (lane == 8)  fw4[24 + 8]  = x;   // fb3 -> q8
            if (lane == 16) fw4[24 + 7]  = x;   // fb4 -> q7
            if (lane == 0) {
#pragma unroll
                for (int fb = 5; fb < 8; fb++) {   // warp-uniform sign bits -> q6,q5,q4
                    const u64 v = ((tid >> fb) & 1) ? f2sub(0ull, x) : x;
                    fw4[24 + (11 - fb)] = v;
                }
            }
        }

        // X/Y for tile bits 8..11 -> qubits 3..0 (terminal: inline)
        vcross_fin(vcross_acc<0>(R, I), fw4, 3);
        vcross_fin(vcross_acc<1>(R, I), fw4, 2);
        vcross_fin(vcross_acc<2>(R, I), fw4, 1);
        vcross_fin(vcross_acc<3>(R, I), fw4, 0);
    }
    __syncthreads();

    // ---- Reduce 32 partial rows, then linear head ----
    if (tid < NFEAT) {
        u64 acc = FW[0][tid];
#pragma unroll
        for (int r = 1; r < 32; r++) acc = f2add(acc, FW[r][tid]);
        FZ[tid] = acc;
    }
    __syncthreads();

    if (tid < 2 * NCLASSES) {
        const int batch = tid / NCLASSES;
        const int c     = tid % NCLASSES;
        const float* fz = (const float*)FZ;     // {b0,b1} interleaved per feature
        float acc = bv[c];
#pragma unroll
        for (int j = 0; j < NFEAT; ++j)
            acc += Wm[c * NFEAT + j] * fz[2 * j + batch];
        out[((size_t)(2 * bidx) + batch) * NCLASSES + c] = acc;
    }
}

extern "C" void kernel_launch(void* const* d_in, const int* in_sizes, int n_in,
                              void* d_out, int out_size)
{
    const float* sv     = (const float*)d_in[0];  // [2048, 4096]
    const float* angles = (const float*)d_in[1];  // [96]
    const float* Wm     = (const float*)d_in[2];  // [10, 36]
    const float* bv     = (const float*)d_in[3];  // [10]
    float* out          = (float*)d_out;          // [2048, 10]
    (void)in_sizes; (void)n_in; (void)out_size;

    const int smem_bytes = DIM * (int)sizeof(longlong2);  // 64 KB dynamic
    cudaFuncSetAttribute(qsim_kernel, cudaFuncAttributeMaxDynamicSharedMemorySize, smem_bytes);
    qsim_kernel<<<1024, THREADS, smem_bytes>>>(sv, angles, Wm, bv, out);
}